// round 6
// baseline (speedup 1.0000x reference)
#include <cuda_runtime.h>
#include <cuda_bf16.h>
#include <mma.h>
#include <math.h>
#include <cstdint>

using namespace nvcuda;

#define BB 2
#define TT 2048
#define DD 1024
#define HH 16
#define HD 64
#define NROWS (BB*TT)      // 4096
#define WINDOW 128
#define MM (1024*1024)

// ---------------- scratch (device globals: allocation-free) ----------------
__device__ float g_q[(size_t)BB*HH*TT*HD];
__device__ float g_k[(size_t)BB*HH*TT*HD];
__device__ float g_v[(size_t)BB*HH*TT*HD];
__device__ __nv_bfloat16 g_xh[(size_t)NROWS*DD];
__device__ __nv_bfloat16 g_xl[(size_t)NROWS*DD];
__device__ __nv_bfloat16 g_wh[(size_t)4*MM];
__device__ __nv_bfloat16 g_wl[(size_t)4*MM];
__device__ __nv_bfloat16 g_ath[(size_t)NROWS*DD];
__device__ __nv_bfloat16 g_atl[(size_t)NROWS*DD];

__device__ __forceinline__ float tf32r(float x){
    unsigned u;
    asm("cvt.rna.tf32.f32 %0, %1;" : "=r"(u) : "f"(x));
    return __uint_as_float(u);
}
__device__ __forceinline__ uint32_t smem_u32(const void* p){
    uint32_t a;
    asm("{ .reg .u64 t; cvta.to.shared.u64 t, %1; cvt.u32.u64 %0, t; }" : "=r"(a) : "l"(p));
    return a;
}
__device__ __forceinline__ void cp16(uint32_t s, const void* g){
    asm volatile("cp.async.cg.shared.global [%0], [%1], 16;" :: "r"(s), "l"(g));
}

// =====================================================================
// split prep: fp32 -> bf16 hi/lo for x and all four weight matrices.
// =====================================================================
__global__ void __launch_bounds__(256) split_kernel(
    const float* __restrict__ x,
    const float* __restrict__ wq, const float* __restrict__ wk,
    const float* __restrict__ wv, const float* __restrict__ wo)
{
    size_t fi = (size_t)blockIdx.x*256 + threadIdx.x;
    const float* src; __nv_bfloat16 *dh, *dl; size_t base;
    if (fi < 1048576){ src = x; dh = g_xh; dl = g_xl; base = fi; }
    else {
        size_t r = fi - 1048576;
        int m = (int)(r >> 18);
        base = r & 262143;
        src = (m==0)?wq:(m==1)?wk:(m==2)?wv:wo;
        dh = g_wh + (size_t)m*MM; dl = g_wl + (size_t)m*MM;
    }
    float4 v = ((const float4*)src)[base];
    size_t e = base*4;
    __nv_bfloat16 h0=__float2bfloat16(v.x), h1=__float2bfloat16(v.y),
                  h2=__float2bfloat16(v.z), h3=__float2bfloat16(v.w);
    *(__nv_bfloat162*)(dh+e)   = __nv_bfloat162(h0,h1);
    *(__nv_bfloat162*)(dh+e+2) = __nv_bfloat162(h2,h3);
    *(__nv_bfloat162*)(dl+e)   = __nv_bfloat162(__float2bfloat16(v.x-__bfloat162float(h0)),
                                                __float2bfloat16(v.y-__bfloat162float(h1)));
    *(__nv_bfloat162*)(dl+e+2) = __nv_bfloat162(__float2bfloat16(v.z-__bfloat162float(h2)),
                                                __float2bfloat16(v.w-__bfloat162float(h3)));
}

// =====================================================================
// GEMM (3xBF16 split, fp32 acc), legacy wmma path.
// CTA: M=256 x N=128, 256 threads / 8 warps (4 M-warps x 2 N-warps).
// Warp tile 64x64 -> 4x4 accum frags.
// Inner loop is TERM-MAJOR: each split term issues 16 INDEPENDENT MMAs,
// so accumulator reuse distance is 16 (was 1 -> RAW-chain stalls).
// 3-stage cp.async pipeline, BK=32, one __syncthreads per chunk.
// =====================================================================
#define NCH 32
#define SSTRIDE 40
#define STAGE_EL 30720                  // bf16 elems per stage
#define STAGE_BY 61440
#define GEMM_SMEM (3*STAGE_BY)          // 184320

__global__ void __launch_bounds__(256) gemm_kernel(float* __restrict__ out, int mode)
{
    extern __shared__ __nv_bfloat16 sb[];
    float* Cs = (float*)sb;                       // [256][132] after mainloop

    const int tid = threadIdx.x, w = tid >> 5, lane = tid & 31;
    const int r0 = blockIdx.y * 256;
    const int nb = blockIdx.x * 128;

    int which, col0;
    const __nv_bfloat16 *A_h, *A_l;
    if (mode == 0){ which = nb >> 10; col0 = nb & 1023; A_h = g_xh; A_l = g_xl; }
    else          { which = 3;        col0 = nb;        A_h = g_ath; A_l = g_atl; }
    const __nv_bfloat16* W_h = g_wh + (size_t)which*MM;
    const __nv_bfloat16* W_l = g_wl + (size_t)which*MM;

    const uint32_t ab = smem_u32(sb);

    auto loadc = [&](int c){
        uint32_t st = ab + (uint32_t)(c % 3) * STAGE_BY;
        int ko = c * 32;
        #pragma unroll
        for (int i = 0; i < 4; i++){               // A: 256 rows x 4 segs of 8 bf16
            int idx = tid + i*256;
            int row = idx >> 2, seg = idx & 3;
            uint32_t so = (uint32_t)(row*80 + seg*16);
            size_t go = (size_t)(r0 + row)*DD + ko + seg*8;
            cp16(st + so,          A_h + go);
            cp16(st + 20480u + so, A_l + go);
        }
        #pragma unroll
        for (int i = 0; i < 2; i++){               // B: 128 rows x 4 segs
            int idx = tid + i*256;
            int row = idx >> 2, seg = idx & 3;
            uint32_t so = (uint32_t)(row*80 + seg*16);
            size_t go = (size_t)(col0 + row)*DD + ko + seg*8;
            cp16(st + 40960u + so, W_h + go);
            cp16(st + 51200u + so, W_l + go);
        }
        asm volatile("cp.async.commit_group;");
    };

    wmma::fragment<wmma::accumulator,16,16,16,float> acc[4][4];
    #pragma unroll
    for (int i = 0; i < 4; i++)
        #pragma unroll
        for (int j = 0; j < 4; j++) wmma::fill_fragment(acc[i][j], 0.0f);

    const int wm = (w >> 1) * 64;      // warp M offset: 0/64/128/192
    const int wn = (w & 1) * 64;       // warp N offset: 0/64

    loadc(0); loadc(1);
    for (int c = 0; c < NCH; c++){
        if (c < NCH-1) asm volatile("cp.async.wait_group 1;");
        else           asm volatile("cp.async.wait_group 0;");
        __syncthreads();
        if (c + 2 < NCH) loadc(c + 2);

        const __nv_bfloat16* s = sb + (c % 3) * STAGE_EL;
        const __nv_bfloat16* sAh = s;
        const __nv_bfloat16* sAl = s + 10240;
        const __nv_bfloat16* sBh = s + 20480;
        const __nv_bfloat16* sBl = s + 25600;

        #pragma unroll
        for (int kk = 0; kk < 32; kk += 16){
            wmma::fragment<wmma::matrix_a,16,16,16,__nv_bfloat16,wmma::row_major> af[4];
            wmma::fragment<wmma::matrix_b,16,16,16,__nv_bfloat16,wmma::col_major> bf[4];

            // ---- term 1: hi * hi  (16 independent MMAs) ----
            #pragma unroll
            for (int i = 0; i < 4; i++)
                wmma::load_matrix_sync(af[i], sAh + (wm + i*16)*SSTRIDE + kk, SSTRIDE);
            #pragma unroll
            for (int j = 0; j < 4; j++)
                wmma::load_matrix_sync(bf[j], sBh + (wn + j*16)*SSTRIDE + kk, SSTRIDE);
            #pragma unroll
            for (int i = 0; i < 4; i++)
                #pragma unroll
                for (int j = 0; j < 4; j++)
                    wmma::mma_sync(acc[i][j], af[i], bf[j], acc[i][j]);

            // ---- term 2: hi * lo ----
            {
                wmma::fragment<wmma::matrix_b,16,16,16,__nv_bfloat16,wmma::col_major> b2[4];
                #pragma unroll
                for (int j = 0; j < 4; j++)
                    wmma::load_matrix_sync(b2[j], sBl + (wn + j*16)*SSTRIDE + kk, SSTRIDE);
                #pragma unroll
                for (int i = 0; i < 4; i++)
                    #pragma unroll
                    for (int j = 0; j < 4; j++)
                        wmma::mma_sync(acc[i][j], af[i], b2[j], acc[i][j]);
            }

            // ---- term 3: lo * hi (reuse af storage for A-lo; bf still = B-hi) ----
            #pragma unroll
            for (int i = 0; i < 4; i++)
                wmma::load_matrix_sync(af[i], sAl + (wm + i*16)*SSTRIDE + kk, SSTRIDE);
            #pragma unroll
            for (int i = 0; i < 4; i++)
                #pragma unroll
                for (int j = 0; j < 4; j++)
                    wmma::mma_sync(acc[i][j], af[i], bf[j], acc[i][j]);
        }
    }
    __syncthreads();

    // stage C in smem [256][132]
    #pragma unroll
    for (int i = 0; i < 4; i++)
        #pragma unroll
        for (int j = 0; j < 4; j++)
            wmma::store_matrix_sync(Cs + (wm + i*16)*132 + wn + j*16,
                                    acc[i][j], 132, wmma::mem_row_major);
    __syncthreads();

    // epilogue: warp w -> rows [w*32, w*32+32); lane covers 4 cols
    #pragma unroll
    for (int rr = 0; rr < 32; rr++){
        int row = w*32 + rr;
        int gt = r0 + row;
        float v0 = Cs[row*132 + lane];
        float v1 = Cs[row*132 + lane + 32];
        float v2 = Cs[row*132 + lane + 64];
        float v3 = Cs[row*132 + lane + 96];
        if (mode == 0){
            float s0 = 1.0f, s1 = 1.0f;
            if (which < 2){
                float ssa = v0*v0 + v1*v1;
                float ssb = v2*v2 + v3*v3;
                #pragma unroll
                for (int o = 16; o; o >>= 1){
                    ssa += __shfl_xor_sync(0xffffffffu, ssa, o);
                    ssb += __shfl_xor_sync(0xffffffffu, ssb, o);
                }
                s0 = 1.0f / fmaxf(sqrtf(ssa), 1e-6f);
                s1 = 1.0f / fmaxf(sqrtf(ssb), 1e-6f);
            }
            int bq = gt >> 11, t = gt & (TT-1);
            float* arr = (which==0) ? g_q : ((which==1) ? g_k : g_v);
            int hh0 = col0 >> 6;
            float* d0 = arr + ((size_t)(bq*HH + hh0  )*TT + t)*HD;
            float* d1 = arr + ((size_t)(bq*HH + hh0+1)*TT + t)*HD;
            d0[lane]      = v0*s0;
            d0[lane + 32] = v1*s0;
            d1[lane]      = v2*s1;
            d1[lane + 32] = v3*s1;
        } else {
            float* d = out + (size_t)gt*DD + nb;
            d[lane]      = v0;
            d[lane + 32] = v1;
            d[lane + 64] = v2;
            d[lane + 96] = v3;
        }
    }
}

// =====================================================================
// Attention kernel (tf32 wmma): one block per (b,h,64-q tile).
// Output written as bf16 hi/lo split (feeds Wo GEMM).
// =====================================================================
#define ATTN_SMEM_FLOATS (64*68 + 192*68 + 192*68 + 64*200)
#define ATTN_SMEM_BYTES  (ATTN_SMEM_FLOATS*4)

__global__ void __launch_bounds__(256) attn_kernel()
{
    extern __shared__ float sm[];
    float* Qs = sm;                  // [64][68]
    float* Ks = sm + 64*68;          // [192][68]
    float* Vs = Ks + 192*68;         // [192][68]
    float* Ss = Vs + 192*68;         // [64][200]

    const int tid = threadIdx.x, w = tid >> 5, lane = tid & 31;
    const int q0 = blockIdx.x * 64;
    const int h  = blockIdx.y, b = blockIdx.z;
    const size_t base = ((size_t)(b*HH + h)*TT)*HD;
    const float* qb = g_q + base;
    const float* kb = g_k + base;
    const float* vb = g_v + base;

    #pragma unroll
    for (int it = 0; it < 4; it++){
        int idx = tid + it*256;
        int row = idx >> 4, c4 = (idx & 15) << 2;
        float4 v = *(const float4*)(qb + (size_t)(q0 + row)*HD + c4);
        int o = row*68 + c4;
        Qs[o]=tf32r(v.x); Qs[o+1]=tf32r(v.y); Qs[o+2]=tf32r(v.z); Qs[o+3]=tf32r(v.w);
    }
    #pragma unroll
    for (int it = 0; it < 12; it++){
        int idx = tid + it*256;
        int row = idx >> 4, c4 = (idx & 15) << 2;
        int jg = q0 + row;
        float4 kv = make_float4(0.f,0.f,0.f,0.f), vv = kv;
        if (jg < TT){
            kv = *(const float4*)(kb + (size_t)jg*HD + c4);
            vv = *(const float4*)(vb + (size_t)jg*HD + c4);
        }
        int o = row*68 + c4;
        Ks[o]=tf32r(kv.x); Ks[o+1]=tf32r(kv.y); Ks[o+2]=tf32r(kv.z); Ks[o+3]=tf32r(kv.w);
        Vs[o]=tf32r(vv.x); Vs[o+1]=tf32r(vv.y); Vs[o+2]=tf32r(vv.z); Vs[o+3]=tf32r(vv.w);
    }
    __syncthreads();

    const int wr = w & 3, wc = w >> 2;

    {   // S[64,192] = Q @ K^T
        wmma::fragment<wmma::accumulator,16,16,8,float> acc[6];
        #pragma unroll
        for (int f = 0; f < 6; f++) wmma::fill_fragment(acc[f], 0.0f);
        #pragma unroll
        for (int d = 0; d < HD; d += 8){
            wmma::fragment<wmma::matrix_a,16,16,8,wmma::precision::tf32,wmma::row_major> af;
            wmma::load_matrix_sync(af, Qs + wr*16*68 + d, 68);
            #pragma unroll
            for (int f = 0; f < 6; f++){
                wmma::fragment<wmma::matrix_b,16,16,8,wmma::precision::tf32,wmma::col_major> bf;
                wmma::load_matrix_sync(bf, Ks + (wc*96 + f*16)*68 + d, 68);
                wmma::mma_sync(acc[f], af, bf, acc[f]);
            }
        }
        #pragma unroll
        for (int f = 0; f < 6; f++)
            wmma::store_matrix_sync(Ss + wr*16*200 + wc*96 + f*16, acc[f], 200,
                                    wmma::mem_row_major);
    }
    __syncthreads();

    const float slope = exp2f(-8.0f * (float)h / 15.0f);
    #pragma unroll
    for (int rr = 0; rr < 8; rr++){
        int row = w*8 + rr;
        float vals[6];
        float m = -INFINITY;
        #pragma unroll
        for (int i = 0; i < 6; i++){
            int col = lane + 32*i;
            bool ok = (col >= row) && (col < row + WINDOW) && (q0 + col < TT);
            float s = ok ? (Ss[row*200 + col] - (float)(col - row)*slope) : -INFINITY;
            vals[i] = s;
            m = fmaxf(m, s);
        }
        #pragma unroll
        for (int o = 16; o; o >>= 1) m = fmaxf(m, __shfl_xor_sync(0xffffffffu, m, o));
        float sum = 0.0f;
        #pragma unroll
        for (int i = 0; i < 6; i++){
            float p = (vals[i] > -INFINITY) ? __expf(vals[i] - m) : 0.0f;
            vals[i] = p; sum += p;
        }
        #pragma unroll
        for (int o = 16; o; o >>= 1) sum += __shfl_xor_sync(0xffffffffu, sum, o);
        float inv = 1.0f / sum;
        #pragma unroll
        for (int i = 0; i < 6; i++){
            int col = lane + 32*i;
            Ss[row*200 + col] = tf32r(vals[i]*inv);
        }
    }
    __syncthreads();

    {   // O[64,64] = P @ V
        wmma::fragment<wmma::accumulator,16,16,8,float> acc[2];
        wmma::fill_fragment(acc[0], 0.0f);
        wmma::fill_fragment(acc[1], 0.0f);
        #pragma unroll
        for (int j = 0; j < 192; j += 8){
            wmma::fragment<wmma::matrix_a,16,16,8,wmma::precision::tf32,wmma::row_major> af;
            wmma::load_matrix_sync(af, Ss + wr*16*200 + j, 200);
            #pragma unroll
            for (int f = 0; f < 2; f++){
                wmma::fragment<wmma::matrix_b,16,16,8,wmma::precision::tf32,wmma::row_major> bf;
                wmma::load_matrix_sync(bf, Vs + j*68 + wc*32 + f*16, 68);
                wmma::mma_sync(acc[f], af, bf, acc[f]);
            }
        }
        wmma::store_matrix_sync(Qs + wr*16*68 + wc*32,      acc[0], 68, wmma::mem_row_major);
        wmma::store_matrix_sync(Qs + wr*16*68 + wc*32 + 16, acc[1], 68, wmma::mem_row_major);
    }
    __syncthreads();

    #pragma unroll
    for (int it = 0; it < 4; it++){             // write split bf16 [B,T,D]
        int idx = tid + it*256;
        int row = idx >> 4, c4 = (idx & 15) << 2;
        float4 v = *(const float4*)(Qs + row*68 + c4);
        size_t o = (size_t)(b*TT + q0 + row)*DD + h*HD + c4;
        __nv_bfloat16 h0=__float2bfloat16(v.x), h1=__float2bfloat16(v.y),
                      h2=__float2bfloat16(v.z), h3=__float2bfloat16(v.w);
        *(__nv_bfloat162*)(g_ath+o)   = __nv_bfloat162(h0,h1);
        *(__nv_bfloat162*)(g_ath+o+2) = __nv_bfloat162(h2,h3);
        *(__nv_bfloat162*)(g_atl+o)   = __nv_bfloat162(__float2bfloat16(v.x-__bfloat162float(h0)),
                                                       __float2bfloat16(v.y-__bfloat162float(h1)));
        *(__nv_bfloat162*)(g_atl+o+2) = __nv_bfloat162(__float2bfloat16(v.z-__bfloat162float(h2)),
                                                       __float2bfloat16(v.w-__bfloat162float(h3)));
    }
}

// =====================================================================
extern "C" void kernel_launch(void* const* d_in, const int* in_sizes, int n_in,
                              void* d_out, int out_size)
{
    const float* x  = (const float*)d_in[0];
    const float* Wq = (const float*)d_in[1];
    const float* Wk = (const float*)d_in[2];
    const float* Wv = (const float*)d_in[3];
    const float* Wo = (const float*)d_in[4];
    float* out = (float*)d_out;

    cudaFuncSetAttribute(gemm_kernel, cudaFuncAttributeMaxDynamicSharedMemorySize,
                         GEMM_SMEM);
    cudaFuncSetAttribute(attn_kernel, cudaFuncAttributeMaxDynamicSharedMemorySize,
                         ATTN_SMEM_BYTES);

    // 0) precision split of x and weights
    split_kernel<<<8192, 256>>>(x, Wq, Wk, Wv, Wo);
    // 1) fused QKV projection + per-head l2norm  [M=4096 x N=3072]
    gemm_kernel<<<dim3(24, 16), 256, GEMM_SMEM>>>(nullptr, 0);
    // 2) sliding-window attention per (b, h, 64-query tile)
    attn_kernel<<<dim3(TT/64, HH, BB), 256, ATTN_SMEM_BYTES>>>();
    // 3) output projection  [M=4096 x N=1024]
    gemm_kernel<<<dim3(8, 16), 256, GEMM_SMEM>>>(out, 1);
}

// round 7
// speedup vs baseline: 1.0708x; 1.0708x over previous
#include <cuda_runtime.h>
#include <cuda_bf16.h>
#include <mma.h>
#include <math.h>
#include <cstdint>

using namespace nvcuda;

#define BB 2
#define TT 2048
#define DD 1024
#define HH 16
#define HD 64
#define NROWS (BB*TT)      // 4096
#define WINDOW 128
#define MM (1024*1024)

// ---------------- scratch (device globals: allocation-free) ----------------
__device__ float g_q[(size_t)BB*HH*TT*HD];
__device__ float g_k[(size_t)BB*HH*TT*HD];
__device__ float g_v[(size_t)BB*HH*TT*HD];
__device__ __nv_bfloat16 g_xh[(size_t)NROWS*DD];
__device__ __nv_bfloat16 g_xl[(size_t)NROWS*DD];
__device__ __nv_bfloat16 g_wh[(size_t)4*MM];
__device__ __nv_bfloat16 g_wl[(size_t)4*MM];
__device__ __nv_bfloat16 g_ath[(size_t)NROWS*DD];
__device__ __nv_bfloat16 g_atl[(size_t)NROWS*DD];

__device__ __forceinline__ float tf32r(float x){
    unsigned u;
    asm("cvt.rna.tf32.f32 %0, %1;" : "=r"(u) : "f"(x));
    return __uint_as_float(u);
}
__device__ __forceinline__ uint32_t smem_u32(const void* p){
    uint32_t a;
    asm("{ .reg .u64 t; cvta.to.shared.u64 t, %1; cvt.u32.u64 %0, t; }" : "=r"(a) : "l"(p));
    return a;
}
__device__ __forceinline__ void cp16(uint32_t s, const void* g){
    asm volatile("cp.async.cg.shared.global [%0], [%1], 16;" :: "r"(s), "l"(g));
}

// =====================================================================
// split prep: fp32 -> bf16 hi/lo for x and all four weight matrices.
// =====================================================================
__global__ void __launch_bounds__(256) split_kernel(
    const float* __restrict__ x,
    const float* __restrict__ wq, const float* __restrict__ wk,
    const float* __restrict__ wv, const float* __restrict__ wo)
{
    size_t fi = (size_t)blockIdx.x*256 + threadIdx.x;
    const float* src; __nv_bfloat16 *dh, *dl; size_t base;
    if (fi < 1048576){ src = x; dh = g_xh; dl = g_xl; base = fi; }
    else {
        size_t r = fi - 1048576;
        int m = (int)(r >> 18);
        base = r & 262143;
        src = (m==0)?wq:(m==1)?wk:(m==2)?wv:wo;
        dh = g_wh + (size_t)m*MM; dl = g_wl + (size_t)m*MM;
    }
    float4 v = ((const float4*)src)[base];
    size_t e = base*4;
    __nv_bfloat16 h0=__float2bfloat16(v.x), h1=__float2bfloat16(v.y),
                  h2=__float2bfloat16(v.z), h3=__float2bfloat16(v.w);
    *(__nv_bfloat162*)(dh+e)   = __nv_bfloat162(h0,h1);
    *(__nv_bfloat162*)(dh+e+2) = __nv_bfloat162(h2,h3);
    *(__nv_bfloat162*)(dl+e)   = __nv_bfloat162(__float2bfloat16(v.x-__bfloat162float(h0)),
                                                __float2bfloat16(v.y-__bfloat162float(h1)));
    *(__nv_bfloat162*)(dl+e+2) = __nv_bfloat162(__float2bfloat16(v.z-__bfloat162float(h2)),
                                                __float2bfloat16(v.w-__bfloat162float(h3)));
}

// =====================================================================
// GEMM (3xBF16 split, fp32 acc), legacy wmma path, 2 CTAs/SM.
// CTA: M=128 x N=128, 256 threads / 8 warps (2 M-warps x 4 N-warps).
// Warp tile 64x32 -> 4x2 accum frags (64 regs). __launch_bounds__(256,2).
// 2-stage cp.async, BK=32. smem 80KB/CTA -> 2 CTAs/SM (16 warps/SM).
// =====================================================================
#define NCH 32
#define SSTRIDE 40
#define SARR 5120                        // 128 rows x 40 el
#define STAGE_EL (4*SARR)                // 20480 el
#define STAGE_BY (STAGE_EL*2)            // 40960 B
#define GEMM_SMEM (2*STAGE_BY)           // 81920 B

__global__ void __launch_bounds__(256, 2) gemm_kernel(float* __restrict__ out, int mode)
{
    extern __shared__ __nv_bfloat16 sb[];
    float* Cs = (float*)sb;                       // [128][132] after mainloop

    const int tid = threadIdx.x, w = tid >> 5, lane = tid & 31;
    const int r0 = blockIdx.y * 128;
    const int nb = blockIdx.x * 128;

    int which, col0;
    const __nv_bfloat16 *A_h, *A_l;
    if (mode == 0){ which = nb >> 10; col0 = nb & 1023; A_h = g_xh; A_l = g_xl; }
    else          { which = 3;        col0 = nb;        A_h = g_ath; A_l = g_atl; }
    const __nv_bfloat16* W_h = g_wh + (size_t)which*MM;
    const __nv_bfloat16* W_l = g_wl + (size_t)which*MM;

    const uint32_t ab = smem_u32(sb);

    // per-chunk load: A/B 128 rows x 32 bf16 (4 x 16B segs), hi+lo
    auto loadc = [&](int c){
        uint32_t st = ab + (uint32_t)(c & 1) * STAGE_BY;
        int ko = c * 32;
        #pragma unroll
        for (int i = 0; i < 2; i++){
            int idx = tid + i*256;                 // 0..511
            int row = idx >> 2, seg = idx & 3;
            uint32_t so = (uint32_t)(row*80 + seg*16);
            size_t goA = (size_t)(r0  + row)*DD + ko + seg*8;
            size_t goB = (size_t)(col0 + row)*DD + ko + seg*8;
            cp16(st + so,          A_h + goA);
            cp16(st + 10240u + so, A_l + goA);
            cp16(st + 20480u + so, W_h + goB);
            cp16(st + 30720u + so, W_l + goB);
        }
        asm volatile("cp.async.commit_group;");
    };

    wmma::fragment<wmma::accumulator,16,16,16,float> acc[4][2];
    #pragma unroll
    for (int i = 0; i < 4; i++)
        #pragma unroll
        for (int j = 0; j < 2; j++) wmma::fill_fragment(acc[i][j], 0.0f);

    const int wm = (w >> 2) * 64;      // warp M offset: 0/64
    const int wn = (w & 3) * 32;       // warp N offset: 0/32/64/96

    loadc(0);
    for (int c = 0; c < NCH; c++){
        if (c < NCH-1){
            loadc(c+1);
            asm volatile("cp.async.wait_group 1;");
        } else {
            asm volatile("cp.async.wait_group 0;");
        }
        __syncthreads();

        const __nv_bfloat16* s = sb + (c & 1) * STAGE_EL;
        const __nv_bfloat16* sAh = s;
        const __nv_bfloat16* sAl = s + SARR;
        const __nv_bfloat16* sBh = s + 2*SARR;
        const __nv_bfloat16* sBl = s + 3*SARR;

        #pragma unroll
        for (int kk = 0; kk < 32; kk += 16){
            wmma::fragment<wmma::matrix_a,16,16,16,__nv_bfloat16,wmma::row_major> af[4];
            wmma::fragment<wmma::matrix_b,16,16,16,__nv_bfloat16,wmma::col_major> bf[2], b2[2];

            #pragma unroll
            for (int i = 0; i < 4; i++)
                wmma::load_matrix_sync(af[i], sAh + (wm + i*16)*SSTRIDE + kk, SSTRIDE);
            #pragma unroll
            for (int j = 0; j < 2; j++){
                wmma::load_matrix_sync(bf[j], sBh + (wn + j*16)*SSTRIDE + kk, SSTRIDE);
                wmma::load_matrix_sync(b2[j], sBl + (wn + j*16)*SSTRIDE + kk, SSTRIDE);
            }
            #pragma unroll
            for (int i = 0; i < 4; i++)
                #pragma unroll
                for (int j = 0; j < 2; j++){
                    wmma::mma_sync(acc[i][j], af[i], bf[j], acc[i][j]);   // hi*hi
                    wmma::mma_sync(acc[i][j], af[i], b2[j], acc[i][j]);   // hi*lo
                }
            #pragma unroll
            for (int i = 0; i < 4; i++)
                wmma::load_matrix_sync(af[i], sAl + (wm + i*16)*SSTRIDE + kk, SSTRIDE);
            #pragma unroll
            for (int i = 0; i < 4; i++)
                #pragma unroll
                for (int j = 0; j < 2; j++)
                    wmma::mma_sync(acc[i][j], af[i], bf[j], acc[i][j]);   // lo*hi
        }
        __syncthreads();
    }

    // stage C in smem [128][132]
    #pragma unroll
    for (int i = 0; i < 4; i++)
        #pragma unroll
        for (int j = 0; j < 2; j++)
            wmma::store_matrix_sync(Cs + (wm + i*16)*132 + wn + j*16,
                                    acc[i][j], 132, wmma::mem_row_major);
    __syncthreads();

    // epilogue: warp w -> rows [w*16, w*16+16); lane covers 4 cols
    #pragma unroll
    for (int rr = 0; rr < 16; rr++){
        int row = w*16 + rr;
        int gt = r0 + row;
        float v0 = Cs[row*132 + lane];
        float v1 = Cs[row*132 + lane + 32];
        float v2 = Cs[row*132 + lane + 64];
        float v3 = Cs[row*132 + lane + 96];
        if (mode == 0){
            float s0 = 1.0f, s1 = 1.0f;
            if (which < 2){
                float ssa = v0*v0 + v1*v1;
                float ssb = v2*v2 + v3*v3;
                #pragma unroll
                for (int o = 16; o; o >>= 1){
                    ssa += __shfl_xor_sync(0xffffffffu, ssa, o);
                    ssb += __shfl_xor_sync(0xffffffffu, ssb, o);
                }
                s0 = 1.0f / fmaxf(sqrtf(ssa), 1e-6f);
                s1 = 1.0f / fmaxf(sqrtf(ssb), 1e-6f);
            }
            int bq = gt >> 11, t = gt & (TT-1);
            float* arr = (which==0) ? g_q : ((which==1) ? g_k : g_v);
            int hh0 = col0 >> 6;
            float* d0 = arr + ((size_t)(bq*HH + hh0  )*TT + t)*HD;
            float* d1 = arr + ((size_t)(bq*HH + hh0+1)*TT + t)*HD;
            d0[lane]      = v0*s0;
            d0[lane + 32] = v1*s0;
            d1[lane]      = v2*s1;
            d1[lane + 32] = v3*s1;
        } else {
            float* d = out + (size_t)gt*DD + nb;
            d[lane]      = v0;
            d[lane + 32] = v1;
            d[lane + 64] = v2;
            d[lane + 96] = v3;
        }
    }
}

// =====================================================================
// Attention kernel (tf32 wmma): one block per (b,h,64-q tile).
// Output written as bf16 hi/lo split (feeds Wo GEMM).
// =====================================================================
#define ATTN_SMEM_FLOATS (64*68 + 192*68 + 192*68 + 64*200)
#define ATTN_SMEM_BYTES  (ATTN_SMEM_FLOATS*4)

__global__ void __launch_bounds__(256) attn_kernel()
{
    extern __shared__ float sm[];
    float* Qs = sm;                  // [64][68]
    float* Ks = sm + 64*68;          // [192][68]
    float* Vs = Ks + 192*68;         // [192][68]
    float* Ss = Vs + 192*68;         // [64][200]

    const int tid = threadIdx.x, w = tid >> 5, lane = tid & 31;
    const int q0 = blockIdx.x * 64;
    const int h  = blockIdx.y, b = blockIdx.z;
    const size_t base = ((size_t)(b*HH + h)*TT)*HD;
    const float* qb = g_q + base;
    const float* kb = g_k + base;
    const float* vb = g_v + base;

    #pragma unroll
    for (int it = 0; it < 4; it++){
        int idx = tid + it*256;
        int row = idx >> 4, c4 = (idx & 15) << 2;
        float4 v = *(const float4*)(qb + (size_t)(q0 + row)*HD + c4);
        int o = row*68 + c4;
        Qs[o]=tf32r(v.x); Qs[o+1]=tf32r(v.y); Qs[o+2]=tf32r(v.z); Qs[o+3]=tf32r(v.w);
    }
    #pragma unroll
    for (int it = 0; it < 12; it++){
        int idx = tid + it*256;
        int row = idx >> 4, c4 = (idx & 15) << 2;
        int jg = q0 + row;
        float4 kv = make_float4(0.f,0.f,0.f,0.f), vv = kv;
        if (jg < TT){
            kv = *(const float4*)(kb + (size_t)jg*HD + c4);
            vv = *(const float4*)(vb + (size_t)jg*HD + c4);
        }
        int o = row*68 + c4;
        Ks[o]=tf32r(kv.x); Ks[o+1]=tf32r(kv.y); Ks[o+2]=tf32r(kv.z); Ks[o+3]=tf32r(kv.w);
        Vs[o]=tf32r(vv.x); Vs[o+1]=tf32r(vv.y); Vs[o+2]=tf32r(vv.z); Vs[o+3]=tf32r(vv.w);
    }
    __syncthreads();

    const int wr = w & 3, wc = w >> 2;

    {   // S[64,192] = Q @ K^T
        wmma::fragment<wmma::accumulator,16,16,8,float> acc[6];
        #pragma unroll
        for (int f = 0; f < 6; f++) wmma::fill_fragment(acc[f], 0.0f);
        #pragma unroll
        for (int d = 0; d < HD; d += 8){
            wmma::fragment<wmma::matrix_a,16,16,8,wmma::precision::tf32,wmma::row_major> af;
            wmma::load_matrix_sync(af, Qs + wr*16*68 + d, 68);
            #pragma unroll
            for (int f = 0; f < 6; f++){
                wmma::fragment<wmma::matrix_b,16,16,8,wmma::precision::tf32,wmma::col_major> bf;
                wmma::load_matrix_sync(bf, Ks + (wc*96 + f*16)*68 + d, 68);
                wmma::mma_sync(acc[f], af, bf, acc[f]);
            }
        }
        #pragma unroll
        for (int f = 0; f < 6; f++)
            wmma::store_matrix_sync(Ss + wr*16*200 + wc*96 + f*16, acc[f], 200,
                                    wmma::mem_row_major);
    }
    __syncthreads();

    const float slope = exp2f(-8.0f * (float)h / 15.0f);
    #pragma unroll
    for (int rr = 0; rr < 8; rr++){
        int row = w*8 + rr;
        float vals[6];
        float m = -INFINITY;
        #pragma unroll
        for (int i = 0; i < 6; i++){
            int col = lane + 32*i;
            bool ok = (col >= row) && (col < row + WINDOW) && (q0 + col < TT);
            float s = ok ? (Ss[row*200 + col] - (float)(col - row)*slope) : -INFINITY;
            vals[i] = s;
            m = fmaxf(m, s);
        }
        #pragma unroll
        for (int o = 16; o; o >>= 1) m = fmaxf(m, __shfl_xor_sync(0xffffffffu, m, o));
        float sum = 0.0f;
        #pragma unroll
        for (int i = 0; i < 6; i++){
            float p = (vals[i] > -INFINITY) ? __expf(vals[i] - m) : 0.0f;
            vals[i] = p; sum += p;
        }
        #pragma unroll
        for (int o = 16; o; o >>= 1) sum += __shfl_xor_sync(0xffffffffu, sum, o);
        float inv = 1.0f / sum;
        #pragma unroll
        for (int i = 0; i < 6; i++){
            int col = lane + 32*i;
            Ss[row*200 + col] = tf32r(vals[i]*inv);
        }
    }
    __syncthreads();

    {   // O[64,64] = P @ V
        wmma::fragment<wmma::accumulator,16,16,8,float> acc[2];
        wmma::fill_fragment(acc[0], 0.0f);
        wmma::fill_fragment(acc[1], 0.0f);
        #pragma unroll
        for (int j = 0; j < 192; j += 8){
            wmma::fragment<wmma::matrix_a,16,16,8,wmma::precision::tf32,wmma::row_major> af;
            wmma::load_matrix_sync(af, Ss + wr*16*200 + j, 200);
            #pragma unroll
            for (int f = 0; f < 2; f++){
                wmma::fragment<wmma::matrix_b,16,16,8,wmma::precision::tf32,wmma::row_major> bf;
                wmma::load_matrix_sync(bf, Vs + j*68 + wc*32 + f*16, 68);
                wmma::mma_sync(acc[f], af, bf, acc[f]);
            }
        }
        wmma::store_matrix_sync(Qs + wr*16*68 + wc*32,      acc[0], 68, wmma::mem_row_major);
        wmma::store_matrix_sync(Qs + wr*16*68 + wc*32 + 16, acc[1], 68, wmma::mem_row_major);
    }
    __syncthreads();

    #pragma unroll
    for (int it = 0; it < 4; it++){             // write split bf16 [B,T,D]
        int idx = tid + it*256;
        int row = idx >> 4, c4 = (idx & 15) << 2;
        float4 v = *(const float4*)(Qs + row*68 + c4);
        size_t o = (size_t)(b*TT + q0 + row)*DD + h*HD + c4;
        __nv_bfloat16 h0=__float2bfloat16(v.x), h1=__float2bfloat16(v.y),
                      h2=__float2bfloat16(v.z), h3=__float2bfloat16(v.w);
        *(__nv_bfloat162*)(g_ath+o)   = __nv_bfloat162(h0,h1);
        *(__nv_bfloat162*)(g_ath+o+2) = __nv_bfloat162(h2,h3);
        *(__nv_bfloat162*)(g_atl+o)   = __nv_bfloat162(__float2bfloat16(v.x-__bfloat162float(h0)),
                                                       __float2bfloat16(v.y-__bfloat162float(h1)));
        *(__nv_bfloat162*)(g_atl+o+2) = __nv_bfloat162(__float2bfloat16(v.z-__bfloat162float(h2)),
                                                       __float2bfloat16(v.w-__bfloat162float(h3)));
    }
}

// =====================================================================
extern "C" void kernel_launch(void* const* d_in, const int* in_sizes, int n_in,
                              void* d_out, int out_size)
{
    const float* x  = (const float*)d_in[0];
    const float* Wq = (const float*)d_in[1];
    const float* Wk = (const float*)d_in[2];
    const float* Wv = (const float*)d_in[3];
    const float* Wo = (const float*)d_in[4];
    float* out = (float*)d_out;

    cudaFuncSetAttribute(gemm_kernel, cudaFuncAttributeMaxDynamicSharedMemorySize,
                         GEMM_SMEM);
    cudaFuncSetAttribute(attn_kernel, cudaFuncAttributeMaxDynamicSharedMemorySize,
                         ATTN_SMEM_BYTES);

    // 0) precision split of x and weights
    split_kernel<<<8192, 256>>>(x, Wq, Wk, Wv, Wo);
    // 1) fused QKV projection + per-head l2norm  [M=4096 x N=3072]
    gemm_kernel<<<dim3(24, 32), 256, GEMM_SMEM>>>(nullptr, 0);
    // 2) sliding-window attention per (b, h, 64-query tile)
    attn_kernel<<<dim3(TT/64, HH, BB), 256, ATTN_SMEM_BYTES>>>();
    // 3) output projection  [M=4096 x N=1024]
    gemm_kernel<<<dim3(8, 32), 256, GEMM_SMEM>>>(out, 1);
}

// round 8
// speedup vs baseline: 1.4400x; 1.3448x over previous
#include <cuda_runtime.h>
#include <cuda_fp16.h>
#include <cuda_bf16.h>
#include <mma.h>
#include <math.h>
#include <cstdint>

using namespace nvcuda;

#define BB 2
#define TT 2048
#define DD 1024
#define HH 16
#define HD 64
#define NROWS (BB*TT)      // 4096
#define WINDOW 128
#define MM (1024*1024)

// ---------------- scratch (device globals: allocation-free) ----------------
__device__ float g_q[(size_t)BB*HH*TT*HD];
__device__ float g_k[(size_t)BB*HH*TT*HD];
__device__ float g_v[(size_t)BB*HH*TT*HD];
__device__ __half g_xh[(size_t)NROWS*DD];    // x split hi/lo (fp16)
__device__ __half g_xl[(size_t)NROWS*DD];
__device__ __half g_wh[(size_t)4*MM];        // 32*W in fp16 (single term)
__device__ __half g_ath[(size_t)NROWS*DD];   // attention out split hi/lo
__device__ __half g_atl[(size_t)NROWS*DD];

__device__ __forceinline__ float tf32r(float x){
    unsigned u;
    asm("cvt.rna.tf32.f32 %0, %1;" : "=r"(u) : "f"(x));
    return __uint_as_float(u);
}
__device__ __forceinline__ uint32_t smem_u32(const void* p){
    uint32_t a;
    asm("{ .reg .u64 t; cvta.to.shared.u64 t, %1; cvt.u32.u64 %0, t; }" : "=r"(a) : "l"(p));
    return a;
}
__device__ __forceinline__ void cp16(uint32_t s, const void* g){
    asm volatile("cp.async.cg.shared.global [%0], [%1], 16;" :: "r"(s), "l"(g));
}

// =====================================================================
// split prep:
//   x  -> fp16 hi + lo  (21-bit effective)
//   W  -> fp16(32*W)    (single term; exact /32 in GEMM epilogue)
// =====================================================================
__global__ void __launch_bounds__(256) split_kernel(
    const float* __restrict__ x,
    const float* __restrict__ wq, const float* __restrict__ wk,
    const float* __restrict__ wv, const float* __restrict__ wo)
{
    size_t fi = (size_t)blockIdx.x*256 + threadIdx.x;
    if (fi < 1048576){
        float4 v = ((const float4*)x)[fi];
        size_t e = fi*4;
        __half h0=__float2half(v.x), h1=__float2half(v.y),
               h2=__float2half(v.z), h3=__float2half(v.w);
        *(half2*)(g_xh+e)   = half2(h0,h1);
        *(half2*)(g_xh+e+2) = half2(h2,h3);
        *(half2*)(g_xl+e)   = half2(__float2half(v.x-__half2float(h0)),
                                    __float2half(v.y-__half2float(h1)));
        *(half2*)(g_xl+e+2) = half2(__float2half(v.z-__half2float(h2)),
                                    __float2half(v.w-__half2float(h3)));
    } else {
        size_t r = fi - 1048576;
        int m = (int)(r >> 18);
        size_t base = r & 262143;
        const float* src = (m==0)?wq:(m==1)?wk:(m==2)?wv:wo;
        float4 v = ((const float4*)src)[base];
        size_t e = (size_t)m*MM + base*4;
        *(half2*)(g_wh+e)   = half2(__float2half(32.0f*v.x), __float2half(32.0f*v.y));
        *(half2*)(g_wh+e+2) = half2(__float2half(32.0f*v.z), __float2half(32.0f*v.w));
    }
}

// =====================================================================
// GEMM (2xFP16 asymmetric split, fp32 acc), 2 CTAs/SM.
// CTA: M=128 x N=128, 256 threads / 8 warps (2 M-warps x 4 N-warps).
// Warp tile 64x32 -> 4x2 accum frags. 2-stage cp.async, BK=32.
// smem stage: Ah[128][40] + Al + Bh = 30720 B; x2 = 61440; Cs needs 67584.
// Terms per kk: acc += a_hi*b ; acc += a_lo*b   (16 MMAs, was 24)
// =====================================================================
#define NCH 32
#define SSTRIDE 40
#define SARR 5120                        // 128 rows x 40 el
#define STAGE_EL (3*SARR)                // 15360 el
#define STAGE_BY (STAGE_EL*2)            // 30720 B
#define GEMM_SMEM 67584                  // max(2*STAGE_BY, 128*132*4)

__global__ void __launch_bounds__(256, 2) gemm_kernel(float* __restrict__ out, int mode)
{
    extern __shared__ __half sb[];
    float* Cs = (float*)sb;                       // [128][132] after mainloop

    const int tid = threadIdx.x, w = tid >> 5, lane = tid & 31;
    const int r0 = blockIdx.y * 128;
    const int nb = blockIdx.x * 128;

    int which, col0;
    const __half *A_h, *A_l;
    if (mode == 0){ which = nb >> 10; col0 = nb & 1023; A_h = g_xh; A_l = g_xl; }
    else          { which = 3;        col0 = nb;        A_h = g_ath; A_l = g_atl; }
    const __half* W_h = g_wh + (size_t)which*MM;

    const uint32_t ab = smem_u32(sb);

    auto loadc = [&](int c){
        uint32_t st = ab + (uint32_t)(c & 1) * STAGE_BY;
        int ko = c * 32;
        #pragma unroll
        for (int i = 0; i < 2; i++){
            int idx = tid + i*256;                 // 0..511
            int row = idx >> 2, seg = idx & 3;
            uint32_t so = (uint32_t)(row*80 + seg*16);
            size_t goA = (size_t)(r0  + row)*DD + ko + seg*8;
            size_t goB = (size_t)(col0 + row)*DD + ko + seg*8;
            cp16(st + so,          A_h + goA);
            cp16(st + 10240u + so, A_l + goA);
            cp16(st + 20480u + so, W_h + goB);
        }
        asm volatile("cp.async.commit_group;");
    };

    wmma::fragment<wmma::accumulator,16,16,16,float> acc[4][2];
    #pragma unroll
    for (int i = 0; i < 4; i++)
        #pragma unroll
        for (int j = 0; j < 2; j++) wmma::fill_fragment(acc[i][j], 0.0f);

    const int wm = (w >> 2) * 64;      // warp M offset: 0/64
    const int wn = (w & 3) * 32;       // warp N offset: 0/32/64/96

    loadc(0);
    for (int c = 0; c < NCH; c++){
        if (c < NCH-1){
            loadc(c+1);
            asm volatile("cp.async.wait_group 1;");
        } else {
            asm volatile("cp.async.wait_group 0;");
        }
        __syncthreads();

        const __half* s = sb + (c & 1) * STAGE_EL;
        const __half* sAh = s;
        const __half* sAl = s + SARR;
        const __half* sBh = s + 2*SARR;

        #pragma unroll
        for (int kk = 0; kk < 32; kk += 16){
            wmma::fragment<wmma::matrix_a,16,16,16,__half,wmma::row_major> af[4];
            wmma::fragment<wmma::matrix_b,16,16,16,__half,wmma::col_major> bf[2];

            #pragma unroll
            for (int i = 0; i < 4; i++)
                wmma::load_matrix_sync(af[i], sAh + (wm + i*16)*SSTRIDE + kk, SSTRIDE);
            #pragma unroll
            for (int j = 0; j < 2; j++)
                wmma::load_matrix_sync(bf[j], sBh + (wn + j*16)*SSTRIDE + kk, SSTRIDE);
            #pragma unroll
            for (int i = 0; i < 4; i++)
                #pragma unroll
                for (int j = 0; j < 2; j++)
                    wmma::mma_sync(acc[i][j], af[i], bf[j], acc[i][j]);   // hi * B

            #pragma unroll
            for (int i = 0; i < 4; i++)
                wmma::load_matrix_sync(af[i], sAl + (wm + i*16)*SSTRIDE + kk, SSTRIDE);
            #pragma unroll
            for (int i = 0; i < 4; i++)
                #pragma unroll
                for (int j = 0; j < 2; j++)
                    wmma::mma_sync(acc[i][j], af[i], bf[j], acc[i][j]);   // lo * B
        }
        __syncthreads();
    }

    // stage C in smem [128][132]  (values are 32x true; /32 or norm in epilogue)
    #pragma unroll
    for (int i = 0; i < 4; i++)
        #pragma unroll
        for (int j = 0; j < 2; j++)
            wmma::store_matrix_sync(Cs + (wm + i*16)*132 + wn + j*16,
                                    acc[i][j], 132, wmma::mem_row_major);
    __syncthreads();

    const float unsc = 0.03125f;   // 1/32
    // epilogue: warp w -> rows [w*16, w*16+16); lane covers 4 cols
    #pragma unroll
    for (int rr = 0; rr < 16; rr++){
        int row = w*16 + rr;
        int gt = r0 + row;
        float v0 = Cs[row*132 + lane];
        float v1 = Cs[row*132 + lane + 32];
        float v2 = Cs[row*132 + lane + 64];
        float v3 = Cs[row*132 + lane + 96];
        if (mode == 0){
            float s0 = unsc, s1 = unsc;
            if (which < 2){                        // l2norm (scale cancels)
                float ssa = v0*v0 + v1*v1;
                float ssb = v2*v2 + v3*v3;
                #pragma unroll
                for (int o = 16; o; o >>= 1){
                    ssa += __shfl_xor_sync(0xffffffffu, ssa, o);
                    ssb += __shfl_xor_sync(0xffffffffu, ssb, o);
                }
                s0 = 1.0f / fmaxf(sqrtf(ssa), 1e-6f);
                s1 = 1.0f / fmaxf(sqrtf(ssb), 1e-6f);
            }
            int bq = gt >> 11, t = gt & (TT-1);
            float* arr = (which==0) ? g_q : ((which==1) ? g_k : g_v);
            int hh0 = col0 >> 6;
            float* d0 = arr + ((size_t)(bq*HH + hh0  )*TT + t)*HD;
            float* d1 = arr + ((size_t)(bq*HH + hh0+1)*TT + t)*HD;
            d0[lane]      = v0*s0;
            d0[lane + 32] = v1*s0;
            d1[lane]      = v2*s1;
            d1[lane + 32] = v3*s1;
        } else {
            float* d = out + (size_t)gt*DD + nb;
            d[lane]      = v0*unsc;
            d[lane + 32] = v1*unsc;
            d[lane + 64] = v2*unsc;
            d[lane + 96] = v3*unsc;
        }
    }
}

// =====================================================================
// Attention kernel (tf32 wmma): one block per (b,h,64-q tile).
// Output written as fp16 hi/lo split (feeds Wo GEMM).
// =====================================================================
#define ATTN_SMEM_FLOATS (64*68 + 192*68 + 192*68 + 64*200)
#define ATTN_SMEM_BYTES  (ATTN_SMEM_FLOATS*4)

__global__ void __launch_bounds__(256) attn_kernel()
{
    extern __shared__ float sm[];
    float* Qs = sm;                  // [64][68]
    float* Ks = sm + 64*68;          // [192][68]
    float* Vs = Ks + 192*68;         // [192][68]
    float* Ss = Vs + 192*68;         // [64][200]

    const int tid = threadIdx.x, w = tid >> 5, lane = tid & 31;
    const int q0 = blockIdx.x * 64;
    const int h  = blockIdx.y, b = blockIdx.z;
    const size_t base = ((size_t)(b*HH + h)*TT)*HD;
    const float* qb = g_q + base;
    const float* kb = g_k + base;
    const float* vb = g_v + base;

    #pragma unroll
    for (int it = 0; it < 4; it++){
        int idx = tid + it*256;
        int row = idx >> 4, c4 = (idx & 15) << 2;
        float4 v = *(const float4*)(qb + (size_t)(q0 + row)*HD + c4);
        int o = row*68 + c4;
        Qs[o]=tf32r(v.x); Qs[o+1]=tf32r(v.y); Qs[o+2]=tf32r(v.z); Qs[o+3]=tf32r(v.w);
    }
    #pragma unroll
    for (int it = 0; it < 12; it++){
        int idx = tid + it*256;
        int row = idx >> 4, c4 = (idx & 15) << 2;
        int jg = q0 + row;
        float4 kv = make_float4(0.f,0.f,0.f,0.f), vv = kv;
        if (jg < TT){
            kv = *(const float4*)(kb + (size_t)jg*HD + c4);
            vv = *(const float4*)(vb + (size_t)jg*HD + c4);
        }
        int o = row*68 + c4;
        Ks[o]=tf32r(kv.x); Ks[o+1]=tf32r(kv.y); Ks[o+2]=tf32r(kv.z); Ks[o+3]=tf32r(kv.w);
        Vs[o]=tf32r(vv.x); Vs[o+1]=tf32r(vv.y); Vs[o+2]=tf32r(vv.z); Vs[o+3]=tf32r(vv.w);
    }
    __syncthreads();

    const int wr = w & 3, wc = w >> 2;

    {   // S[64,192] = Q @ K^T
        wmma::fragment<wmma::accumulator,16,16,8,float> acc[6];
        #pragma unroll
        for (int f = 0; f < 6; f++) wmma::fill_fragment(acc[f], 0.0f);
        #pragma unroll
        for (int d = 0; d < HD; d += 8){
            wmma::fragment<wmma::matrix_a,16,16,8,wmma::precision::tf32,wmma::row_major> af;
            wmma::load_matrix_sync(af, Qs + wr*16*68 + d, 68);
            #pragma unroll
            for (int f = 0; f < 6; f++){
                wmma::fragment<wmma::matrix_b,16,16,8,wmma::precision::tf32,wmma::col_major> bf;
                wmma::load_matrix_sync(bf, Ks + (wc*96 + f*16)*68 + d, 68);
                wmma::mma_sync(acc[f], af, bf, acc[f]);
            }
        }
        #pragma unroll
        for (int f = 0; f < 6; f++)
            wmma::store_matrix_sync(Ss + wr*16*200 + wc*96 + f*16, acc[f], 200,
                                    wmma::mem_row_major);
    }
    __syncthreads();

    const float slope = exp2f(-8.0f * (float)h / 15.0f);
    #pragma unroll
    for (int rr = 0; rr < 8; rr++){
        int row = w*8 + rr;
        float vals[6];
        float m = -INFINITY;
        #pragma unroll
        for (int i = 0; i < 6; i++){
            int col = lane + 32*i;
            bool ok = (col >= row) && (col < row + WINDOW) && (q0 + col < TT);
            float s = ok ? (Ss[row*200 + col] - (float)(col - row)*slope) : -INFINITY;
            vals[i] = s;
            m = fmaxf(m, s);
        }
        #pragma unroll
        for (int o = 16; o; o >>= 1) m = fmaxf(m, __shfl_xor_sync(0xffffffffu, m, o));
        float sum = 0.0f;
        #pragma unroll
        for (int i = 0; i < 6; i++){
            float p = (vals[i] > -INFINITY) ? __expf(vals[i] - m) : 0.0f;
            vals[i] = p; sum += p;
        }
        #pragma unroll
        for (int o = 16; o; o >>= 1) sum += __shfl_xor_sync(0xffffffffu, sum, o);
        float inv = 1.0f / sum;
        #pragma unroll
        for (int i = 0; i < 6; i++){
            int col = lane + 32*i;
            Ss[row*200 + col] = tf32r(vals[i]*inv);
        }
    }
    __syncthreads();

    {   // O[64,64] = P @ V
        wmma::fragment<wmma::accumulator,16,16,8,float> acc[2];
        wmma::fill_fragment(acc[0], 0.0f);
        wmma::fill_fragment(acc[1], 0.0f);
        #pragma unroll
        for (int j = 0; j < 192; j += 8){
            wmma::fragment<wmma::matrix_a,16,16,8,wmma::precision::tf32,wmma::row_major> af;
            wmma::load_matrix_sync(af, Ss + wr*16*200 + j, 200);
            #pragma unroll
            for (int f = 0; f < 2; f++){
                wmma::fragment<wmma::matrix_b,16,16,8,wmma::precision::tf32,wmma::row_major> bf;
                wmma::load_matrix_sync(bf, Vs + j*68 + wc*32 + f*16, 68);
                wmma::mma_sync(acc[f], af, bf, acc[f]);
            }
        }
        wmma::store_matrix_sync(Qs + wr*16*68 + wc*32,      acc[0], 68, wmma::mem_row_major);
        wmma::store_matrix_sync(Qs + wr*16*68 + wc*32 + 16, acc[1], 68, wmma::mem_row_major);
    }
    __syncthreads();

    #pragma unroll
    for (int it = 0; it < 4; it++){             // write split fp16 [B,T,D]
        int idx = tid + it*256;
        int row = idx >> 4, c4 = (idx & 15) << 2;
        float4 v = *(const float4*)(Qs + row*68 + c4);
        size_t o = (size_t)(b*TT + q0 + row)*DD + h*HD + c4;
        __half h0=__float2half(v.x), h1=__float2half(v.y),
               h2=__float2half(v.z), h3=__float2half(v.w);
        *(half2*)(g_ath+o)   = half2(h0,h1);
        *(half2*)(g_ath+o+2) = half2(h2,h3);
        *(half2*)(g_atl+o)   = half2(__float2half(v.x-__half2float(h0)),
                                     __float2half(v.y-__half2float(h1)));
        *(half2*)(g_atl+o+2) = half2(__float2half(v.z-__half2float(h2)),
                                     __float2half(v.w-__half2float(h3)));
    }
}

// =====================================================================
extern "C" void kernel_launch(void* const* d_in, const int* in_sizes, int n_in,
                              void* d_out, int out_size)
{
    const float* x  = (const float*)d_in[0];
    const float* Wq = (const float*)d_in[1];
    const float* Wk = (const float*)d_in[2];
    const float* Wv = (const float*)d_in[3];
    const float* Wo = (const float*)d_in[4];
    float* out = (float*)d_out;

    cudaFuncSetAttribute(gemm_kernel, cudaFuncAttributeMaxDynamicSharedMemorySize,
                         GEMM_SMEM);
    cudaFuncSetAttribute(attn_kernel, cudaFuncAttributeMaxDynamicSharedMemorySize,
                         ATTN_SMEM_BYTES);

    // 0) precision split of x (hi/lo fp16) and weights (fp16, x32)
    split_kernel<<<8192, 256>>>(x, Wq, Wk, Wv, Wo);
    // 1) fused QKV projection + per-head l2norm  [M=4096 x N=3072]
    gemm_kernel<<<dim3(24, 32), 256, GEMM_SMEM>>>(nullptr, 0);
    // 2) sliding-window attention per (b, h, 64-query tile)
    attn_kernel<<<dim3(TT/64, HH, BB), 256, ATTN_SMEM_BYTES>>>();
    // 3) output projection  [M=4096 x N=1024]
    gemm_kernel<<<dim3(8, 32), 256, GEMM_SMEM>>>(out, 1);
}

// round 9
// speedup vs baseline: 1.8883x; 1.3113x over previous
#include <cuda_runtime.h>
#include <cuda_fp16.h>
#include <mma.h>
#include <math.h>
#include <cstdint>

using namespace nvcuda;

#define BB 2
#define TT 2048
#define DD 1024
#define HH 16
#define HD 64
#define NROWS (BB*TT)      // 4096
#define WINDOW 128
#define MM (1024*1024)

// ---------------- scratch (device globals: allocation-free) ----------------
__device__ __half g_q[(size_t)BB*HH*TT*HD];   // normalized q (fp16)
__device__ __half g_k[(size_t)BB*HH*TT*HD];   // normalized k (fp16)
__device__ __half g_v[(size_t)BB*HH*TT*HD];   // v (fp16)
__device__ __half g_xh[(size_t)NROWS*DD];     // x split hi/lo (fp16)
__device__ __half g_xl[(size_t)NROWS*DD];
__device__ __half g_wh[(size_t)4*MM];         // 32*W in fp16 (single term)
__device__ __half g_ath[(size_t)NROWS*DD];    // attention out split hi/lo
__device__ __half g_atl[(size_t)NROWS*DD];

__device__ __forceinline__ uint32_t smem_u32(const void* p){
    uint32_t a;
    asm("{ .reg .u64 t; cvta.to.shared.u64 t, %1; cvt.u32.u64 %0, t; }" : "=r"(a) : "l"(p));
    return a;
}
__device__ __forceinline__ void cp16(uint32_t s, const void* g){
    asm volatile("cp.async.cg.shared.global [%0], [%1], 16;" :: "r"(s), "l"(g));
}

// =====================================================================
// split prep: x -> fp16 hi+lo ; W -> fp16(32*W)
// =====================================================================
__global__ void __launch_bounds__(256) split_kernel(
    const float* __restrict__ x,
    const float* __restrict__ wq, const float* __restrict__ wk,
    const float* __restrict__ wv, const float* __restrict__ wo)
{
    size_t fi = (size_t)blockIdx.x*256 + threadIdx.x;
    if (fi < 1048576){
        float4 v = ((const float4*)x)[fi];
        size_t e = fi*4;
        __half h0=__float2half(v.x), h1=__float2half(v.y),
               h2=__float2half(v.z), h3=__float2half(v.w);
        *(half2*)(g_xh+e)   = half2(h0,h1);
        *(half2*)(g_xh+e+2) = half2(h2,h3);
        *(half2*)(g_xl+e)   = half2(__float2half(v.x-__half2float(h0)),
                                    __float2half(v.y-__half2float(h1)));
        *(half2*)(g_xl+e+2) = half2(__float2half(v.z-__half2float(h2)),
                                    __float2half(v.w-__half2float(h3)));
    } else {
        size_t r = fi - 1048576;
        int m = (int)(r >> 18);
        size_t base = r & 262143;
        const float* src = (m==0)?wq:(m==1)?wk:(m==2)?wv:wo;
        float4 v = ((const float4*)src)[base];
        size_t e = (size_t)m*MM + base*4;
        *(half2*)(g_wh+e)   = half2(__float2half(32.0f*v.x), __float2half(32.0f*v.y));
        *(half2*)(g_wh+e+2) = half2(__float2half(32.0f*v.z), __float2half(32.0f*v.w));
    }
}

// =====================================================================
// GEMM (fp16, fp32 acc), 2 CTAs/SM. CTA 128x128, warp 64x32, BK=32.
//   mode 0, which<2 (q,k): A single term  (8 MMAs/kk)   -> l2norm epilogue
//   mode 0, which=2 (v):   A hi+lo terms  (16 MMAs/kk)
//   mode 1 (Wo):           A hi+lo terms; fp32 out, /32
// =====================================================================
#define NCH 32
#define SSTRIDE 40
#define SARR 5120                        // 128 rows x 40 el
#define STAGE_EL (3*SARR)                // 15360 el
#define STAGE_BY (STAGE_EL*2)            // 30720 B
#define GEMM_SMEM 67584                  // max(2*STAGE_BY, 128*132*4)

__global__ void __launch_bounds__(256, 2) gemm_kernel(float* __restrict__ out, int mode)
{
    extern __shared__ __half sb[];
    float* Cs = (float*)sb;                       // [128][132] after mainloop

    const int tid = threadIdx.x, w = tid >> 5, lane = tid & 31;
    const int r0 = blockIdx.y * 128;
    const int nb = blockIdx.x * 128;

    int which, col0;
    const __half *A_h, *A_l;
    if (mode == 0){ which = nb >> 10; col0 = nb & 1023; A_h = g_xh; A_l = g_xl; }
    else          { which = 3;        col0 = nb;        A_h = g_ath; A_l = g_atl; }
    const __half* W_h = g_wh + (size_t)which*MM;
    const bool twoA = !(mode == 0 && which < 2);

    const uint32_t ab = smem_u32(sb);

    auto loadc = [&](int c){
        uint32_t st = ab + (uint32_t)(c & 1) * STAGE_BY;
        int ko = c * 32;
        #pragma unroll
        for (int i = 0; i < 2; i++){
            int idx = tid + i*256;                 // 0..511
            int row = idx >> 2, seg = idx & 3;
            uint32_t so = (uint32_t)(row*80 + seg*16);
            size_t goA = (size_t)(r0  + row)*DD + ko + seg*8;
            size_t goB = (size_t)(col0 + row)*DD + ko + seg*8;
            cp16(st + so,          A_h + goA);
            if (twoA) cp16(st + 10240u + so, A_l + goA);
            cp16(st + 20480u + so, W_h + goB);
        }
        asm volatile("cp.async.commit_group;");
    };

    wmma::fragment<wmma::accumulator,16,16,16,float> acc[4][2];
    #pragma unroll
    for (int i = 0; i < 4; i++)
        #pragma unroll
        for (int j = 0; j < 2; j++) wmma::fill_fragment(acc[i][j], 0.0f);

    const int wm = (w >> 2) * 64;      // warp M offset: 0/64
    const int wn = (w & 3) * 32;       // warp N offset: 0/32/64/96

    loadc(0);
    for (int c = 0; c < NCH; c++){
        if (c < NCH-1){
            loadc(c+1);
            asm volatile("cp.async.wait_group 1;");
        } else {
            asm volatile("cp.async.wait_group 0;");
        }
        __syncthreads();

        const __half* s = sb + (c & 1) * STAGE_EL;
        const __half* sAh = s;
        const __half* sAl = s + SARR;
        const __half* sBh = s + 2*SARR;

        #pragma unroll
        for (int kk = 0; kk < 32; kk += 16){
            wmma::fragment<wmma::matrix_a,16,16,16,__half,wmma::row_major> af[4];
            wmma::fragment<wmma::matrix_b,16,16,16,__half,wmma::col_major> bf[2];

            #pragma unroll
            for (int i = 0; i < 4; i++)
                wmma::load_matrix_sync(af[i], sAh + (wm + i*16)*SSTRIDE + kk, SSTRIDE);
            #pragma unroll
            for (int j = 0; j < 2; j++)
                wmma::load_matrix_sync(bf[j], sBh + (wn + j*16)*SSTRIDE + kk, SSTRIDE);
            #pragma unroll
            for (int i = 0; i < 4; i++)
                #pragma unroll
                for (int j = 0; j < 2; j++)
                    wmma::mma_sync(acc[i][j], af[i], bf[j], acc[i][j]);   // hi * B

            if (twoA){
                #pragma unroll
                for (int i = 0; i < 4; i++)
                    wmma::load_matrix_sync(af[i], sAl + (wm + i*16)*SSTRIDE + kk, SSTRIDE);
                #pragma unroll
                for (int i = 0; i < 4; i++)
                    #pragma unroll
                    for (int j = 0; j < 2; j++)
                        wmma::mma_sync(acc[i][j], af[i], bf[j], acc[i][j]);   // lo * B
            }
        }
        __syncthreads();
    }

    // stage C in smem [128][132]  (values 32x true)
    #pragma unroll
    for (int i = 0; i < 4; i++)
        #pragma unroll
        for (int j = 0; j < 2; j++)
            wmma::store_matrix_sync(Cs + (wm + i*16)*132 + wn + j*16,
                                    acc[i][j], 132, wmma::mem_row_major);
    __syncthreads();

    const float unsc = 0.03125f;   // 1/32
    #pragma unroll
    for (int rr = 0; rr < 16; rr++){
        int row = w*16 + rr;
        int gt = r0 + row;
        float v0 = Cs[row*132 + lane];
        float v1 = Cs[row*132 + lane + 32];
        float v2 = Cs[row*132 + lane + 64];
        float v3 = Cs[row*132 + lane + 96];
        if (mode == 0){
            float s0 = unsc, s1 = unsc;
            if (which < 2){                        // l2norm (scale cancels)
                float ssa = v0*v0 + v1*v1;
                float ssb = v2*v2 + v3*v3;
                #pragma unroll
                for (int o = 16; o; o >>= 1){
                    ssa += __shfl_xor_sync(0xffffffffu, ssa, o);
                    ssb += __shfl_xor_sync(0xffffffffu, ssb, o);
                }
                s0 = 1.0f / fmaxf(sqrtf(ssa), 1e-6f);
                s1 = 1.0f / fmaxf(sqrtf(ssb), 1e-6f);
            }
            int bq = gt >> 11, t = gt & (TT-1);
            __half* arr = (which==0) ? g_q : ((which==1) ? g_k : g_v);
            int hh0 = col0 >> 6;
            __half* d0 = arr + ((size_t)(bq*HH + hh0  )*TT + t)*HD;
            __half* d1 = arr + ((size_t)(bq*HH + hh0+1)*TT + t)*HD;
            d0[lane]      = __float2half(v0*s0);
            d0[lane + 32] = __float2half(v1*s0);
            d1[lane]      = __float2half(v2*s1);
            d1[lane + 32] = __float2half(v3*s1);
        } else {
            float* d = out + (size_t)gt*DD + nb;
            d[lane]      = v0*unsc;
            d[lane + 32] = v1*unsc;
            d[lane + 64] = v2*unsc;
            d[lane + 96] = v3*unsc;
        }
    }
}

// =====================================================================
// Attention (fp16 wmma, fp32 softmax): one block per (b,h,64-q tile).
// smem (half base): Qs[64][72] Ks[192][72] Vs[192][72] | Ssf f32[64][200]
//                   | Ps half[64][200]   total 141312 B
// =====================================================================
#define ATTN_SMEM_BYTES 141312

__global__ void __launch_bounds__(256) attn_kernel()
{
    extern __shared__ __half sm[];
    __half* Qs = sm;                          // [64][72]
    __half* Ks = sm + 4608;                   // [192][72]
    __half* Vs = sm + 18432;                  // [192][72]
    float*  Ssf = (float*)(sm + 32256);       // [64][200] f32 (S, later O[64][68])
    __half* Ps  = sm + 57856;                 // [64][200] half

    const int tid = threadIdx.x, w = tid >> 5, lane = tid & 31;
    const int q0 = blockIdx.x * 64;
    const int h  = blockIdx.y, b = blockIdx.z;
    const size_t base = ((size_t)(b*HH + h)*TT)*HD;
    const __half* qb = g_q + base;
    const __half* kb = g_k + base;
    const __half* vb = g_v + base;

    #pragma unroll
    for (int it = 0; it < 2; it++){           // Q: 64x64 half (8-half segs)
        int idx = tid + it*256;
        int row = idx >> 3, seg = idx & 7;
        uint4 v = *(const uint4*)(qb + (size_t)(q0 + row)*HD + seg*8);
        *(uint4*)(Qs + row*72 + seg*8) = v;
    }
    #pragma unroll
    for (int it = 0; it < 6; it++){           // K,V: 192x64 (zero-pad past T)
        int idx = tid + it*256;
        int row = idx >> 3, seg = idx & 7;
        int jg = q0 + row;
        uint4 kv = make_uint4(0,0,0,0), vv = make_uint4(0,0,0,0);
        if (jg < TT){
            kv = *(const uint4*)(kb + (size_t)jg*HD + seg*8);
            vv = *(const uint4*)(vb + (size_t)jg*HD + seg*8);
        }
        *(uint4*)(Ks + row*72 + seg*8) = kv;
        *(uint4*)(Vs + row*72 + seg*8) = vv;
    }
    __syncthreads();

    const int wr = w & 3, wc = w >> 2;        // 4 row-bands x 2 col-bands

    {   // S[64,192] = Q @ K^T  (fp16, 24 MMAs/warp)
        wmma::fragment<wmma::accumulator,16,16,16,float> acc[6];
        #pragma unroll
        for (int f = 0; f < 6; f++) wmma::fill_fragment(acc[f], 0.0f);
        #pragma unroll
        for (int d = 0; d < HD; d += 16){
            wmma::fragment<wmma::matrix_a,16,16,16,__half,wmma::row_major> af;
            wmma::load_matrix_sync(af, Qs + wr*16*72 + d, 72);
            #pragma unroll
            for (int f = 0; f < 6; f++){
                wmma::fragment<wmma::matrix_b,16,16,16,__half,wmma::col_major> bf;
                wmma::load_matrix_sync(bf, Ks + (wc*96 + f*16)*72 + d, 72);
                wmma::mma_sync(acc[f], af, bf, acc[f]);
            }
        }
        #pragma unroll
        for (int f = 0; f < 6; f++)
            wmma::store_matrix_sync(Ssf + wr*16*200 + wc*96 + f*16, acc[f], 200,
                                    wmma::mem_row_major);
    }
    __syncthreads();

    // softmax with ALiBi + sliding-window mask; P written to Ps (fp16)
    const float slope = exp2f(-8.0f * (float)h / 15.0f);
    #pragma unroll
    for (int rr = 0; rr < 8; rr++){
        int row = w*8 + rr;
        float vals[6];
        float m = -INFINITY;
        #pragma unroll
        for (int i = 0; i < 6; i++){
            int col = lane + 32*i;
            bool ok = (col >= row) && (col < row + WINDOW) && (q0 + col < TT);
            float s = ok ? (Ssf[row*200 + col] - (float)(col - row)*slope) : -INFINITY;
            vals[i] = s;
            m = fmaxf(m, s);
        }
        #pragma unroll
        for (int o = 16; o; o >>= 1) m = fmaxf(m, __shfl_xor_sync(0xffffffffu, m, o));
        float sum = 0.0f;
        #pragma unroll
        for (int i = 0; i < 6; i++){
            float p = (vals[i] > -INFINITY) ? __expf(vals[i] - m) : 0.0f;
            vals[i] = p; sum += p;
        }
        #pragma unroll
        for (int o = 16; o; o >>= 1) sum += __shfl_xor_sync(0xffffffffu, sum, o);
        float inv = 1.0f / sum;
        #pragma unroll
        for (int i = 0; i < 6; i++){
            int col = lane + 32*i;
            Ps[row*200 + col] = __float2half(vals[i]*inv);
        }
    }
    __syncthreads();

    {   // O[64,64] = P @ V  (fp16, 24 MMAs/warp); stage O into Ssf [64][68]
        wmma::fragment<wmma::accumulator,16,16,16,float> acc[2];
        wmma::fill_fragment(acc[0], 0.0f);
        wmma::fill_fragment(acc[1], 0.0f);
        #pragma unroll
        for (int j = 0; j < 192; j += 16){
            wmma::fragment<wmma::matrix_a,16,16,16,__half,wmma::row_major> af;
            wmma::load_matrix_sync(af, Ps + wr*16*200 + j, 200);
            #pragma unroll
            for (int f = 0; f < 2; f++){
                wmma::fragment<wmma::matrix_b,16,16,16,__half,wmma::row_major> bf;
                wmma::load_matrix_sync(bf, Vs + j*72 + wc*32 + f*16, 72);
                wmma::mma_sync(acc[f], af, bf, acc[f]);
            }
        }
        wmma::store_matrix_sync(Ssf + wr*16*68 + wc*32,      acc[0], 68, wmma::mem_row_major);
        wmma::store_matrix_sync(Ssf + wr*16*68 + wc*32 + 16, acc[1], 68, wmma::mem_row_major);
    }
    __syncthreads();

    #pragma unroll
    for (int it = 0; it < 4; it++){             // write split fp16 [B,T,D]
        int idx = tid + it*256;
        int row = idx >> 4, c4 = (idx & 15) << 2;
        float4 v = *(const float4*)(Ssf + row*68 + c4);
        size_t o = (size_t)(b*TT + q0 + row)*DD + h*HD + c4;
        __half h0=__float2half(v.x), h1=__float2half(v.y),
               h2=__float2half(v.z), h3=__float2half(v.w);
        *(half2*)(g_ath+o)   = half2(h0,h1);
        *(half2*)(g_ath+o+2) = half2(h2,h3);
        *(half2*)(g_atl+o)   = half2(__float2half(v.x-__half2float(h0)),
                                     __float2half(v.y-__half2float(h1)));
        *(half2*)(g_atl+o+2) = half2(__float2half(v.z-__half2float(h2)),
                                     __float2half(v.w-__half2float(h3)));
    }
}

// =====================================================================
extern "C" void kernel_launch(void* const* d_in, const int* in_sizes, int n_in,
                              void* d_out, int out_size)
{
    const float* x  = (const float*)d_in[0];
    const float* Wq = (const float*)d_in[1];
    const float* Wk = (const float*)d_in[2];
    const float* Wv = (const float*)d_in[3];
    const float* Wo = (const float*)d_in[4];
    float* out = (float*)d_out;

    cudaFuncSetAttribute(gemm_kernel, cudaFuncAttributeMaxDynamicSharedMemorySize,
                         GEMM_SMEM);
    cudaFuncSetAttribute(attn_kernel, cudaFuncAttributeMaxDynamicSharedMemorySize,
                         ATTN_SMEM_BYTES);

    // 0) precision split of x (hi/lo fp16) and weights (fp16, x32)
    split_kernel<<<8192, 256>>>(x, Wq, Wk, Wv, Wo);
    // 1) fused QKV projection + per-head l2norm  [M=4096 x N=3072]
    gemm_kernel<<<dim3(24, 32), 256, GEMM_SMEM>>>(nullptr, 0);
    // 2) sliding-window attention per (b, h, 64-query tile)
    attn_kernel<<<dim3(TT/64, HH, BB), 256, ATTN_SMEM_BYTES>>>();
    // 3) output projection  [M=4096 x N=1024]
    gemm_kernel<<<dim3(8, 32), 256, GEMM_SMEM>>>(out, 1);
}

// round 10
// speedup vs baseline: 2.5182x; 1.3336x over previous
#include <cuda_runtime.h>
#include <cuda_fp16.h>
#include <mma.h>
#include <math.h>
#include <cstdint>

using namespace nvcuda;

#define BB 2
#define TT 2048
#define DD 1024
#define HH 16
#define HD 64
#define NROWS (BB*TT)      // 4096
#define WINDOW 128
#define MM (1024*1024)

// ---------------- scratch (device globals: allocation-free) ----------------
__device__ __half g_q[(size_t)BB*HH*TT*HD];   // normalized q (fp16)
__device__ __half g_k[(size_t)BB*HH*TT*HD];   // normalized k (fp16)
__device__ __half g_v[(size_t)BB*HH*TT*HD];   // v (fp16)
__device__ __half g_xh[(size_t)NROWS*DD];     // x (fp16)
__device__ __half g_wh[(size_t)4*MM];         // 32*W (fp16)
__device__ __half g_ath[(size_t)NROWS*DD];    // attention out (fp16)

__device__ __forceinline__ uint32_t smem_u32(const void* p){
    uint32_t a;
    asm("{ .reg .u64 t; cvta.to.shared.u64 t, %1; cvt.u32.u64 %0, t; }" : "=r"(a) : "l"(p));
    return a;
}
__device__ __forceinline__ void cp16(uint32_t s, const void* g){
    asm volatile("cp.async.cg.shared.global [%0], [%1], 16;" :: "r"(s), "l"(g));
}

// =====================================================================
// split prep: x -> fp16 ; W -> fp16(32*W)
// =====================================================================
__global__ void __launch_bounds__(256) split_kernel(
    const float* __restrict__ x,
    const float* __restrict__ wq, const float* __restrict__ wk,
    const float* __restrict__ wv, const float* __restrict__ wo)
{
    size_t fi = (size_t)blockIdx.x*256 + threadIdx.x;
    if (fi < 1048576){
        float4 v = ((const float4*)x)[fi];
        size_t e = fi*4;
        *(half2*)(g_xh+e)   = half2(__float2half(v.x), __float2half(v.y));
        *(half2*)(g_xh+e+2) = half2(__float2half(v.z), __float2half(v.w));
    } else {
        size_t r = fi - 1048576;
        int m = (int)(r >> 18);
        size_t base = r & 262143;
        const float* src = (m==0)?wq:(m==1)?wk:(m==2)?wv:wo;
        float4 v = ((const float4*)src)[base];
        size_t e = (size_t)m*MM + base*4;
        *(half2*)(g_wh+e)   = half2(__float2half(32.0f*v.x), __float2half(32.0f*v.y));
        *(half2*)(g_wh+e+2) = half2(__float2half(32.0f*v.z), __float2half(32.0f*v.w));
    }
}

// =====================================================================
// GEMM (plain fp16, fp32 acc), 2 CTAs/SM. CTA 128x128, warp 64x32, BK=32.
//   mode 0: A = x fp16, W = Wq|Wk|Wv block; l2norm epilogue for q,k.
//   mode 1: A = att fp16, W = Wo; fp32 out, /32.
// smem stage: A[128][40] + B[128][40] half = 20480 B; x2 = 40960; Cs 67584.
// =====================================================================
#define NCH 32
#define SSTRIDE 40
#define SARR 5120                        // 128 rows x 40 el
#define STAGE_EL (2*SARR)                // 10240 el
#define STAGE_BY (STAGE_EL*2)            // 20480 B
#define GEMM_SMEM 67584                  // max(2*STAGE_BY, 128*132*4)

__global__ void __launch_bounds__(256, 2) gemm_kernel(float* __restrict__ out, int mode)
{
    extern __shared__ __half sb[];
    float* Cs = (float*)sb;                       // [128][132] after mainloop

    const int tid = threadIdx.x, w = tid >> 5, lane = tid & 31;
    const int r0 = blockIdx.y * 128;
    const int nb = blockIdx.x * 128;

    int which, col0;
    const __half* A_h;
    if (mode == 0){ which = nb >> 10; col0 = nb & 1023; A_h = g_xh; }
    else          { which = 3;        col0 = nb;        A_h = g_ath; }
    const __half* W_h = g_wh + (size_t)which*MM;

    const uint32_t ab = smem_u32(sb);

    auto loadc = [&](int c){
        uint32_t st = ab + (uint32_t)(c & 1) * STAGE_BY;
        int ko = c * 32;
        #pragma unroll
        for (int i = 0; i < 2; i++){
            int idx = tid + i*256;                 // 0..511
            int row = idx >> 2, seg = idx & 3;
            uint32_t so = (uint32_t)(row*80 + seg*16);
            cp16(st + so,          A_h + (size_t)(r0  + row)*DD + ko + seg*8);
            cp16(st + 10240u + so, W_h + (size_t)(col0 + row)*DD + ko + seg*8);
        }
        asm volatile("cp.async.commit_group;");
    };

    wmma::fragment<wmma::accumulator,16,16,16,float> acc[4][2];
    #pragma unroll
    for (int i = 0; i < 4; i++)
        #pragma unroll
        for (int j = 0; j < 2; j++) wmma::fill_fragment(acc[i][j], 0.0f);

    const int wm = (w >> 2) * 64;      // warp M offset: 0/64
    const int wn = (w & 3) * 32;       // warp N offset: 0/32/64/96

    loadc(0);
    for (int c = 0; c < NCH; c++){
        if (c < NCH-1){
            loadc(c+1);
            asm volatile("cp.async.wait_group 1;");
        } else {
            asm volatile("cp.async.wait_group 0;");
        }
        __syncthreads();

        const __half* s = sb + (c & 1) * STAGE_EL;
        const __half* sA = s;
        const __half* sB = s + SARR;

        #pragma unroll
        for (int kk = 0; kk < 32; kk += 16){
            wmma::fragment<wmma::matrix_a,16,16,16,__half,wmma::row_major> af[4];
            wmma::fragment<wmma::matrix_b,16,16,16,__half,wmma::col_major> bf[2];
            #pragma unroll
            for (int i = 0; i < 4; i++)
                wmma::load_matrix_sync(af[i], sA + (wm + i*16)*SSTRIDE + kk, SSTRIDE);
            #pragma unroll
            for (int j = 0; j < 2; j++)
                wmma::load_matrix_sync(bf[j], sB + (wn + j*16)*SSTRIDE + kk, SSTRIDE);
            #pragma unroll
            for (int i = 0; i < 4; i++)
                #pragma unroll
                for (int j = 0; j < 2; j++)
                    wmma::mma_sync(acc[i][j], af[i], bf[j], acc[i][j]);
        }
        __syncthreads();
    }

    // stage C in smem [128][132]  (values 32x true)
    #pragma unroll
    for (int i = 0; i < 4; i++)
        #pragma unroll
        for (int j = 0; j < 2; j++)
            wmma::store_matrix_sync(Cs + (wm + i*16)*132 + wn + j*16,
                                    acc[i][j], 132, wmma::mem_row_major);
    __syncthreads();

    const float unsc = 0.03125f;   // 1/32
    #pragma unroll
    for (int rr = 0; rr < 16; rr++){
        int row = w*16 + rr;
        int gt = r0 + row;
        float v0 = Cs[row*132 + lane];
        float v1 = Cs[row*132 + lane + 32];
        float v2 = Cs[row*132 + lane + 64];
        float v3 = Cs[row*132 + lane + 96];
        if (mode == 0){
            float s0 = unsc, s1 = unsc;
            if (which < 2){                        // l2norm (scale cancels)
                float ssa = v0*v0 + v1*v1;
                float ssb = v2*v2 + v3*v3;
                #pragma unroll
                for (int o = 16; o; o >>= 1){
                    ssa += __shfl_xor_sync(0xffffffffu, ssa, o);
                    ssb += __shfl_xor_sync(0xffffffffu, ssb, o);
                }
                s0 = 1.0f / fmaxf(sqrtf(ssa), 1e-6f);
                s1 = 1.0f / fmaxf(sqrtf(ssb), 1e-6f);
            }
            int bq = gt >> 11, t = gt & (TT-1);
            __half* arr = (which==0) ? g_q : ((which==1) ? g_k : g_v);
            int hh0 = col0 >> 6;
            __half* d0 = arr + ((size_t)(bq*HH + hh0  )*TT + t)*HD;
            __half* d1 = arr + ((size_t)(bq*HH + hh0+1)*TT + t)*HD;
            d0[lane]      = __float2half(v0*s0);
            d0[lane + 32] = __float2half(v1*s0);
            d1[lane]      = __float2half(v2*s1);
            d1[lane + 32] = __float2half(v3*s1);
        } else {
            float* d = out + (size_t)gt*DD + nb;
            d[lane]      = v0*unsc;
            d[lane + 32] = v1*unsc;
            d[lane + 64] = v2*unsc;
            d[lane + 96] = v3*unsc;
        }
    }
}

// =====================================================================
// Attention (fp16 wmma, fp32 softmax): one block per (b,h,64-q tile).
// smem (half base): Qs[64][72] Ks[192][72] Vs[192][72] | Ssf f32[64][200]
//                   | Ps half[64][200]   total 141312 B
// =====================================================================
#define ATTN_SMEM_BYTES 141312

__global__ void __launch_bounds__(256) attn_kernel()
{
    extern __shared__ __half sm[];
    __half* Qs = sm;                          // [64][72]
    __half* Ks = sm + 4608;                   // [192][72]
    __half* Vs = sm + 18432;                  // [192][72]
    float*  Ssf = (float*)(sm + 32256);       // [64][200] f32 (S, later O[64][68])
    __half* Ps  = sm + 57856;                 // [64][200] half

    const int tid = threadIdx.x, w = tid >> 5, lane = tid & 31;
    const int q0 = blockIdx.x * 64;
    const int h  = blockIdx.y, b = blockIdx.z;
    const size_t base = ((size_t)(b*HH + h)*TT)*HD;
    const __half* qb = g_q + base;
    const __half* kb = g_k + base;
    const __half* vb = g_v + base;

    #pragma unroll
    for (int it = 0; it < 2; it++){           // Q: 64x64 half (8-half segs)
        int idx = tid + it*256;
        int row = idx >> 3, seg = idx & 7;
        uint4 v = *(const uint4*)(qb + (size_t)(q0 + row)*HD + seg*8);
        *(uint4*)(Qs + row*72 + seg*8) = v;
    }
    #pragma unroll
    for (int it = 0; it < 6; it++){           // K,V: 192x64 (zero-pad past T)
        int idx = tid + it*256;
        int row = idx >> 3, seg = idx & 7;
        int jg = q0 + row;
        uint4 kv = make_uint4(0,0,0,0), vv = make_uint4(0,0,0,0);
        if (jg < TT){
            kv = *(const uint4*)(kb + (size_t)jg*HD + seg*8);
            vv = *(const uint4*)(vb + (size_t)jg*HD + seg*8);
        }
        *(uint4*)(Ks + row*72 + seg*8) = kv;
        *(uint4*)(Vs + row*72 + seg*8) = vv;
    }
    __syncthreads();

    const int wr = w & 3, wc = w >> 2;        // 4 row-bands x 2 col-bands

    {   // S[64,192] = Q @ K^T  (fp16)
        wmma::fragment<wmma::accumulator,16,16,16,float> acc[6];
        #pragma unroll
        for (int f = 0; f < 6; f++) wmma::fill_fragment(acc[f], 0.0f);
        #pragma unroll
        for (int d = 0; d < HD; d += 16){
            wmma::fragment<wmma::matrix_a,16,16,16,__half,wmma::row_major> af;
            wmma::load_matrix_sync(af, Qs + wr*16*72 + d, 72);
            #pragma unroll
            for (int f = 0; f < 6; f++){
                wmma::fragment<wmma::matrix_b,16,16,16,__half,wmma::col_major> bf;
                wmma::load_matrix_sync(bf, Ks + (wc*96 + f*16)*72 + d, 72);
                wmma::mma_sync(acc[f], af, bf, acc[f]);
            }
        }
        #pragma unroll
        for (int f = 0; f < 6; f++)
            wmma::store_matrix_sync(Ssf + wr*16*200 + wc*96 + f*16, acc[f], 200,
                                    wmma::mem_row_major);
    }
    __syncthreads();

    // softmax with ALiBi + sliding-window mask; P written to Ps (fp16)
    const float slope = exp2f(-8.0f * (float)h / 15.0f);
    #pragma unroll
    for (int rr = 0; rr < 8; rr++){
        int row = w*8 + rr;
        float vals[6];
        float m = -INFINITY;
        #pragma unroll
        for (int i = 0; i < 6; i++){
            int col = lane + 32*i;
            bool ok = (col >= row) && (col < row + WINDOW) && (q0 + col < TT);
            float s = ok ? (Ssf[row*200 + col] - (float)(col - row)*slope) : -INFINITY;
            vals[i] = s;
            m = fmaxf(m, s);
        }
        #pragma unroll
        for (int o = 16; o; o >>= 1) m = fmaxf(m, __shfl_xor_sync(0xffffffffu, m, o));
        float sum = 0.0f;
        #pragma unroll
        for (int i = 0; i < 6; i++){
            float p = (vals[i] > -INFINITY) ? __expf(vals[i] - m) : 0.0f;
            vals[i] = p; sum += p;
        }
        #pragma unroll
        for (int o = 16; o; o >>= 1) sum += __shfl_xor_sync(0xffffffffu, sum, o);
        float inv = 1.0f / sum;
        #pragma unroll
        for (int i = 0; i < 6; i++){
            int col = lane + 32*i;
            Ps[row*200 + col] = __float2half(vals[i]*inv);
        }
    }
    __syncthreads();

    {   // O[64,64] = P @ V  (fp16); stage O into Ssf [64][68]
        wmma::fragment<wmma::accumulator,16,16,16,float> acc[2];
        wmma::fill_fragment(acc[0], 0.0f);
        wmma::fill_fragment(acc[1], 0.0f);
        #pragma unroll
        for (int j = 0; j < 192; j += 16){
            wmma::fragment<wmma::matrix_a,16,16,16,__half,wmma::row_major> af;
            wmma::load_matrix_sync(af, Ps + wr*16*200 + j, 200);
            #pragma unroll
            for (int f = 0; f < 2; f++){
                wmma::fragment<wmma::matrix_b,16,16,16,__half,wmma::row_major> bf;
                wmma::load_matrix_sync(bf, Vs + j*72 + wc*32 + f*16, 72);
                wmma::mma_sync(acc[f], af, bf, acc[f]);
            }
        }
        wmma::store_matrix_sync(Ssf + wr*16*68 + wc*32,      acc[0], 68, wmma::mem_row_major);
        wmma::store_matrix_sync(Ssf + wr*16*68 + wc*32 + 16, acc[1], 68, wmma::mem_row_major);
    }
    __syncthreads();

    #pragma unroll
    for (int it = 0; it < 4; it++){             // write fp16 [B,T,D]
        int idx = tid + it*256;
        int row = idx >> 4, c4 = (idx & 15) << 2;
        float4 v = *(const float4*)(Ssf + row*68 + c4);
        size_t o = (size_t)(b*TT + q0 + row)*DD + h*HD + c4;
        *(half2*)(g_ath+o)   = half2(__float2half(v.x), __float2half(v.y));
        *(half2*)(g_ath+o+2) = half2(__float2half(v.z), __float2half(v.w));
    }
}

// =====================================================================
extern "C" void kernel_launch(void* const* d_in, const int* in_sizes, int n_in,
                              void* d_out, int out_size)
{
    const float* x  = (const float*)d_in[0];
    const float* Wq = (const float*)d_in[1];
    const float* Wk = (const float*)d_in[2];
    const float* Wv = (const float*)d_in[3];
    const float* Wo = (const float*)d_in[4];
    float* out = (float*)d_out;

    cudaFuncSetAttribute(gemm_kernel, cudaFuncAttributeMaxDynamicSharedMemorySize,
                         GEMM_SMEM);
    cudaFuncSetAttribute(attn_kernel, cudaFuncAttributeMaxDynamicSharedMemorySize,
                         ATTN_SMEM_BYTES);

    // 0) fp16 conversion of x and weights (x32)
    split_kernel<<<8192, 256>>>(x, Wq, Wk, Wv, Wo);
    // 1) fused QKV projection + per-head l2norm  [M=4096 x N=3072]
    gemm_kernel<<<dim3(24, 32), 256, GEMM_SMEM>>>(nullptr, 0);
    // 2) sliding-window attention per (b, h, 64-query tile)
    attn_kernel<<<dim3(TT/64, HH, BB), 256, ATTN_SMEM_BYTES>>>();
    // 3) output projection  [M=4096 x N=1024]
    gemm_kernel<<<dim3(8, 32), 256, GEMM_SMEM>>>(out, 1);
}

// round 11
// speedup vs baseline: 2.7382x; 1.0874x over previous
#include <cuda_runtime.h>
#include <cuda_fp16.h>
#include <mma.h>
#include <math.h>
#include <cstdint>

using namespace nvcuda;

#define BB 2
#define TT 2048
#define DD 1024
#define HH 16
#define HD 64
#define NROWS (BB*TT)      // 4096
#define WINDOW 128
#define MM (1024*1024)

// ---------------- scratch (device globals: allocation-free) ----------------
__device__ __half g_q[(size_t)BB*HH*TT*HD];   // normalized q (fp16)
__device__ __half g_k[(size_t)BB*HH*TT*HD];   // normalized k (fp16)
__device__ __half g_v[(size_t)BB*HH*TT*HD];   // v (fp16)
__device__ __half g_xh[(size_t)NROWS*DD];     // x (fp16)
__device__ __half g_wh[(size_t)4*MM];         // 32*W (fp16)
__device__ __half g_ath[(size_t)NROWS*DD];    // attention out (fp16)

__device__ __forceinline__ uint32_t smem_u32(const void* p){
    uint32_t a;
    asm("{ .reg .u64 t; cvta.to.shared.u64 t, %1; cvt.u32.u64 %0, t; }" : "=r"(a) : "l"(p));
    return a;
}
__device__ __forceinline__ void cp16(uint32_t s, const void* g){
    asm volatile("cp.async.cg.shared.global [%0], [%1], 16;" :: "r"(s), "l"(g));
}

// =====================================================================
// split prep: x -> fp16 ; W -> fp16(32*W)
// =====================================================================
__global__ void __launch_bounds__(256) split_kernel(
    const float* __restrict__ x,
    const float* __restrict__ wq, const float* __restrict__ wk,
    const float* __restrict__ wv, const float* __restrict__ wo)
{
    size_t fi = (size_t)blockIdx.x*256 + threadIdx.x;
    if (fi < 1048576){
        float4 v = ((const float4*)x)[fi];
        size_t e = fi*4;
        *(half2*)(g_xh+e)   = half2(__float2half(v.x), __float2half(v.y));
        *(half2*)(g_xh+e+2) = half2(__float2half(v.z), __float2half(v.w));
    } else {
        size_t r = fi - 1048576;
        int m = (int)(r >> 18);
        size_t base = r & 262143;
        const float* src = (m==0)?wq:(m==1)?wk:(m==2)?wv:wo;
        float4 v = ((const float4*)src)[base];
        size_t e = (size_t)m*MM + base*4;
        *(half2*)(g_wh+e)   = half2(__float2half(32.0f*v.x), __float2half(32.0f*v.y));
        *(half2*)(g_wh+e+2) = half2(__float2half(32.0f*v.z), __float2half(32.0f*v.w));
    }
}

// =====================================================================
// GEMM (plain fp16, fp32 acc), 2 CTAs/SM. CTA 128x128, warp 64x32.
// BK=64: 32 MMAs per sync epoch (halved sync/wait overhead vs BK=32).
// smem stage: A[128][72] + B[128][72] half = 36864 B; x2 = 73728 B.
// =====================================================================
#define NCH 16
#define SSTRIDE 72
#define SARR 9216                        // 128 rows x 72 el
#define STAGE_EL (2*SARR)                // 18432 el
#define STAGE_BY (STAGE_EL*2)            // 36864 B
#define GEMM_SMEM 73728

__global__ void __launch_bounds__(256, 2) gemm_kernel(float* __restrict__ out, int mode)
{
    extern __shared__ __half sb[];
    float* Cs = (float*)sb;                       // [128][132] after mainloop

    const int tid = threadIdx.x, w = tid >> 5, lane = tid & 31;
    const int r0 = blockIdx.y * 128;
    const int nb = blockIdx.x * 128;

    int which, col0;
    const __half* A_h;
    if (mode == 0){ which = nb >> 10; col0 = nb & 1023; A_h = g_xh; }
    else          { which = 3;        col0 = nb;        A_h = g_ath; }
    const __half* W_h = g_wh + (size_t)which*MM;

    const uint32_t ab = smem_u32(sb);

    auto loadc = [&](int c){
        uint32_t st = ab + (uint32_t)(c & 1) * STAGE_BY;
        int ko = c * 64;
        #pragma unroll
        for (int i = 0; i < 4; i++){
            int idx = tid + i*256;                 // 0..1023: 128 rows x 8 segs
            int row = idx >> 3, seg = idx & 7;
            uint32_t so = (uint32_t)(row*144 + seg*16);
            cp16(st + so,          A_h + (size_t)(r0  + row)*DD + ko + seg*8);
            cp16(st + 18432u + so, W_h + (size_t)(col0 + row)*DD + ko + seg*8);
        }
        asm volatile("cp.async.commit_group;");
    };

    wmma::fragment<wmma::accumulator,16,16,16,float> acc[4][2];
    #pragma unroll
    for (int i = 0; i < 4; i++)
        #pragma unroll
        for (int j = 0; j < 2; j++) wmma::fill_fragment(acc[i][j], 0.0f);

    const int wm = (w >> 2) * 64;      // warp M offset: 0/64
    const int wn = (w & 3) * 32;       // warp N offset: 0/32/64/96

    loadc(0);
    for (int c = 0; c < NCH; c++){
        if (c < NCH-1){
            loadc(c+1);
            asm volatile("cp.async.wait_group 1;");
        } else {
            asm volatile("cp.async.wait_group 0;");
        }
        __syncthreads();

        const __half* s = sb + (c & 1) * STAGE_EL;
        const __half* sA = s;
        const __half* sB = s + SARR;

        #pragma unroll
        for (int kk = 0; kk < 64; kk += 16){
            wmma::fragment<wmma::matrix_a,16,16,16,__half,wmma::row_major> af[4];
            wmma::fragment<wmma::matrix_b,16,16,16,__half,wmma::col_major> bf[2];
            #pragma unroll
            for (int i = 0; i < 4; i++)
                wmma::load_matrix_sync(af[i], sA + (wm + i*16)*SSTRIDE + kk, SSTRIDE);
            #pragma unroll
            for (int j = 0; j < 2; j++)
                wmma::load_matrix_sync(bf[j], sB + (wn + j*16)*SSTRIDE + kk, SSTRIDE);
            #pragma unroll
            for (int i = 0; i < 4; i++)
                #pragma unroll
                for (int j = 0; j < 2; j++)
                    wmma::mma_sync(acc[i][j], af[i], bf[j], acc[i][j]);
        }
        __syncthreads();
    }

    // stage C in smem [128][132]  (values 32x true)
    #pragma unroll
    for (int i = 0; i < 4; i++)
        #pragma unroll
        for (int j = 0; j < 2; j++)
            wmma::store_matrix_sync(Cs + (wm + i*16)*132 + wn + j*16,
                                    acc[i][j], 132, wmma::mem_row_major);
    __syncthreads();

    const float unsc = 0.03125f;   // 1/32
    #pragma unroll
    for (int rr = 0; rr < 16; rr++){
        int row = w*16 + rr;
        int gt = r0 + row;
        float v0 = Cs[row*132 + lane];
        float v1 = Cs[row*132 + lane + 32];
        float v2 = Cs[row*132 + lane + 64];
        float v3 = Cs[row*132 + lane + 96];
        if (mode == 0){
            float s0 = unsc, s1 = unsc;
            if (which < 2){                        // l2norm (scale cancels)
                float ssa = v0*v0 + v1*v1;
                float ssb = v2*v2 + v3*v3;
                #pragma unroll
                for (int o = 16; o; o >>= 1){
                    ssa += __shfl_xor_sync(0xffffffffu, ssa, o);
                    ssb += __shfl_xor_sync(0xffffffffu, ssb, o);
                }
                s0 = 1.0f / fmaxf(sqrtf(ssa), 1e-6f);
                s1 = 1.0f / fmaxf(sqrtf(ssb), 1e-6f);
            }
            int bq = gt >> 11, t = gt & (TT-1);
            __half* arr = (which==0) ? g_q : ((which==1) ? g_k : g_v);
            int hh0 = col0 >> 6;
            __half* d0 = arr + ((size_t)(bq*HH + hh0  )*TT + t)*HD;
            __half* d1 = arr + ((size_t)(bq*HH + hh0+1)*TT + t)*HD;
            d0[lane]      = __float2half(v0*s0);
            d0[lane + 32] = __float2half(v1*s0);
            d1[lane]      = __float2half(v2*s1);
            d1[lane + 32] = __float2half(v3*s1);
        } else {
            float* d = out + (size_t)gt*DD + nb;
            d[lane]      = v0*unsc;
            d[lane + 32] = v1*unsc;
            d[lane + 64] = v2*unsc;
            d[lane + 96] = v3*unsc;
        }
    }
}

// =====================================================================
// Attention (fp16 wmma, fp32 softmax): one block per (b,h,64-q tile).
// Window-tile skipping: score tile (row band wr, col tile tc) is live
// only when wr <= tc <= wr+8  -> 9/12 tiles in QK and PV.
// smem (half base): Qs[64][72] Ks[192][72] Vs[192][72] | Ssf f32[64][200]
//                   | Ps half[64][200]   total 141312 B
// =====================================================================
#define ATTN_SMEM_BYTES 141312

__global__ void __launch_bounds__(256) attn_kernel()
{
    extern __shared__ __half sm[];
    __half* Qs = sm;                          // [64][72]
    __half* Ks = sm + 4608;                   // [192][72]
    __half* Vs = sm + 18432;                  // [192][72]
    float*  Ssf = (float*)(sm + 32256);       // [64][200] f32 (S, later O[64][68])
    __half* Ps  = sm + 57856;                 // [64][200] half

    const int tid = threadIdx.x, w = tid >> 5, lane = tid & 31;
    const int q0 = blockIdx.x * 64;
    const int h  = blockIdx.y, b = blockIdx.z;
    const size_t base = ((size_t)(b*HH + h)*TT)*HD;
    const __half* qb = g_q + base;
    const __half* kb = g_k + base;
    const __half* vb = g_v + base;

    #pragma unroll
    for (int it = 0; it < 2; it++){           // Q: 64x64 half
        int idx = tid + it*256;
        int row = idx >> 3, seg = idx & 7;
        uint4 v = *(const uint4*)(qb + (size_t)(q0 + row)*HD + seg*8);
        *(uint4*)(Qs + row*72 + seg*8) = v;
    }
    #pragma unroll
    for (int it = 0; it < 6; it++){           // K,V: 192x64 (zero-pad past T)
        int idx = tid + it*256;
        int row = idx >> 3, seg = idx & 7;
        int jg = q0 + row;
        uint4 kv = make_uint4(0,0,0,0), vv = make_uint4(0,0,0,0);
        if (jg < TT){
            kv = *(const uint4*)(kb + (size_t)jg*HD + seg*8);
            vv = *(const uint4*)(vb + (size_t)jg*HD + seg*8);
        }
        *(uint4*)(Ks + row*72 + seg*8) = kv;
        *(uint4*)(Vs + row*72 + seg*8) = vv;
    }
    __syncthreads();

    const int wr = w & 3, wc = w >> 2;        // 4 row-bands x 2 col-bands

    {   // S[64,192] = Q @ K^T  (fp16), window-live tiles only
        wmma::fragment<wmma::accumulator,16,16,16,float> acc[6];
        #pragma unroll
        for (int f = 0; f < 6; f++) wmma::fill_fragment(acc[f], 0.0f);
        #pragma unroll
        for (int d = 0; d < HD; d += 16){
            wmma::fragment<wmma::matrix_a,16,16,16,__half,wmma::row_major> af;
            wmma::load_matrix_sync(af, Qs + wr*16*72 + d, 72);
            #pragma unroll
            for (int f = 0; f < 6; f++){
                int tc = wc*6 + f;
                if (tc >= wr && tc <= wr + 8){
                    wmma::fragment<wmma::matrix_b,16,16,16,__half,wmma::col_major> bf;
                    wmma::load_matrix_sync(bf, Ks + (wc*96 + f*16)*72 + d, 72);
                    wmma::mma_sync(acc[f], af, bf, acc[f]);
                }
            }
        }
        #pragma unroll
        for (int f = 0; f < 6; f++){
            int tc = wc*6 + f;
            if (tc >= wr && tc <= wr + 8)
                wmma::store_matrix_sync(Ssf + wr*16*200 + wc*96 + f*16, acc[f], 200,
                                        wmma::mem_row_major);
        }
    }
    __syncthreads();

    // softmax with ALiBi + sliding-window mask; P (incl. zeros) -> Ps fp16
    const float slope = exp2f(-8.0f * (float)h / 15.0f);
    #pragma unroll
    for (int rr = 0; rr < 8; rr++){
        int row = w*8 + rr;
        float vals[6];
        float m = -INFINITY;
        #pragma unroll
        for (int i = 0; i < 6; i++){
            int col = lane + 32*i;
            bool ok = (col >= row) && (col < row + WINDOW) && (q0 + col < TT);
            float s = ok ? (Ssf[row*200 + col] - (float)(col - row)*slope) : -INFINITY;
            vals[i] = s;
            m = fmaxf(m, s);
        }
        #pragma unroll
        for (int o = 16; o; o >>= 1) m = fmaxf(m, __shfl_xor_sync(0xffffffffu, m, o));
        float sum = 0.0f;
        #pragma unroll
        for (int i = 0; i < 6; i++){
            float p = (vals[i] > -INFINITY) ? __expf(vals[i] - m) : 0.0f;
            vals[i] = p; sum += p;
        }
        #pragma unroll
        for (int o = 16; o; o >>= 1) sum += __shfl_xor_sync(0xffffffffu, sum, o);
        float inv = 1.0f / sum;
        #pragma unroll
        for (int i = 0; i < 6; i++){
            int col = lane + 32*i;
            Ps[row*200 + col] = __float2half(vals[i]*inv);
        }
    }
    __syncthreads();

    {   // O[64,64] = P @ V  (fp16), live P-tiles only; stage O in Ssf [64][68]
        wmma::fragment<wmma::accumulator,16,16,16,float> acc[2];
        wmma::fill_fragment(acc[0], 0.0f);
        wmma::fill_fragment(acc[1], 0.0f);
        #pragma unroll
        for (int tj = 0; tj < 12; tj++){
            if (tj >= wr && tj <= wr + 8){
                wmma::fragment<wmma::matrix_a,16,16,16,__half,wmma::row_major> af;
                wmma::load_matrix_sync(af, Ps + wr*16*200 + tj*16, 200);
                #pragma unroll
                for (int f = 0; f < 2; f++){
                    wmma::fragment<wmma::matrix_b,16,16,16,__half,wmma::row_major> bf;
                    wmma::load_matrix_sync(bf, Vs + tj*16*72 + wc*32 + f*16, 72);
                    wmma::mma_sync(acc[f], af, bf, acc[f]);
                }
            }
        }
        wmma::store_matrix_sync(Ssf + wr*16*68 + wc*32,      acc[0], 68, wmma::mem_row_major);
        wmma::store_matrix_sync(Ssf + wr*16*68 + wc*32 + 16, acc[1], 68, wmma::mem_row_major);
    }
    __syncthreads();

    #pragma unroll
    for (int it = 0; it < 4; it++){             // write fp16 [B,T,D]
        int idx = tid + it*256;
        int row = idx >> 4, c4 = (idx & 15) << 2;
        float4 v = *(const float4*)(Ssf + row*68 + c4);
        size_t o = (size_t)(b*TT + q0 + row)*DD + h*HD + c4;
        *(half2*)(g_ath+o)   = half2(__float2half(v.x), __float2half(v.y));
        *(half2*)(g_ath+o+2) = half2(__float2half(v.z), __float2half(v.w));
    }
}

// =====================================================================
extern "C" void kernel_launch(void* const* d_in, const int* in_sizes, int n_in,
                              void* d_out, int out_size)
{
    const float* x  = (const float*)d_in[0];
    const float* Wq = (const float*)d_in[1];
    const float* Wk = (const float*)d_in[2];
    const float* Wv = (const float*)d_in[3];
    const float* Wo = (const float*)d_in[4];
    float* out = (float*)d_out;

    cudaFuncSetAttribute(gemm_kernel, cudaFuncAttributeMaxDynamicSharedMemorySize,
                         GEMM_SMEM);
    cudaFuncSetAttribute(attn_kernel, cudaFuncAttributeMaxDynamicSharedMemorySize,
                         ATTN_SMEM_BYTES);

    // 0) fp16 conversion of x and weights (x32)
    split_kernel<<<8192, 256>>>(x, Wq, Wk, Wv, Wo);
    // 1) fused QKV projection + per-head l2norm  [M=4096 x N=3072]
    gemm_kernel<<<dim3(24, 32), 256, GEMM_SMEM>>>(nullptr, 0);
    // 2) sliding-window attention per (b, h, 64-query tile)
    attn_kernel<<<dim3(TT/64, HH, BB), 256, ATTN_SMEM_BYTES>>>();
    // 3) output projection  [M=4096 x N=1024]
    gemm_kernel<<<dim3(8, 32), 256, GEMM_SMEM>>>(out, 1);
}

// round 12
// speedup vs baseline: 2.8604x; 1.0446x over previous
#include <cuda_runtime.h>
#include <cuda_fp16.h>
#include <mma.h>
#include <math.h>
#include <cstdint>

using namespace nvcuda;

#define BB 2
#define TT 2048
#define DD 1024
#define HH 16
#define HD 64
#define NROWS (BB*TT)      // 4096
#define WINDOW 128
#define MM (1024*1024)

// ---------------- scratch (device globals: allocation-free) ----------------
__device__ __half g_q[(size_t)BB*HH*TT*HD];   // normalized q (fp16)
__device__ __half g_k[(size_t)BB*HH*TT*HD];   // normalized k (fp16)
__device__ __half g_v[(size_t)BB*HH*TT*HD];   // v (fp16)
__device__ __half g_xh[(size_t)NROWS*DD];     // x (fp16)
__device__ __half g_wh[(size_t)4*MM];         // 32*W (fp16)
__device__ __half g_ath[(size_t)NROWS*DD];    // attention out (fp16)

__device__ __forceinline__ uint32_t smem_u32(const void* p){
    uint32_t a;
    asm("{ .reg .u64 t; cvta.to.shared.u64 t, %1; cvt.u32.u64 %0, t; }" : "=r"(a) : "l"(p));
    return a;
}
__device__ __forceinline__ void cp16(uint32_t s, const void* g){
    asm volatile("cp.async.cg.shared.global [%0], [%1], 16;" :: "r"(s), "l"(g));
}

// =====================================================================
// split prep: x -> fp16 ; W -> fp16(32*W)
// =====================================================================
__global__ void __launch_bounds__(256) split_kernel(
    const float* __restrict__ x,
    const float* __restrict__ wq, const float* __restrict__ wk,
    const float* __restrict__ wv, const float* __restrict__ wo)
{
    size_t fi = (size_t)blockIdx.x*256 + threadIdx.x;
    if (fi < 1048576){
        float4 v = ((const float4*)x)[fi];
        size_t e = fi*4;
        *(half2*)(g_xh+e)   = half2(__float2half(v.x), __float2half(v.y));
        *(half2*)(g_xh+e+2) = half2(__float2half(v.z), __float2half(v.w));
    } else {
        size_t r = fi - 1048576;
        int m = (int)(r >> 18);
        size_t base = r & 262143;
        const float* src = (m==0)?wq:(m==1)?wk:(m==2)?wv:wo;
        float4 v = ((const float4*)src)[base];
        size_t e = (size_t)m*MM + base*4;
        *(half2*)(g_wh+e)   = half2(__float2half(32.0f*v.x), __float2half(32.0f*v.y));
        *(half2*)(g_wh+e+2) = half2(__float2half(32.0f*v.z), __float2half(32.0f*v.w));
    }
}

// =====================================================================
// GEMM (plain fp16, fp32 acc), 2 CTAs/SM. CTA 128x128, warp 64x32, BK=64.
// (unchanged from R11 — at the legacy-HMMA instruction-rate ceiling)
// =====================================================================
#define NCH 16
#define SSTRIDE 72
#define SARR 9216                        // 128 rows x 72 el
#define STAGE_EL (2*SARR)                // 18432 el
#define STAGE_BY (STAGE_EL*2)            // 36864 B
#define GEMM_SMEM 73728

__global__ void __launch_bounds__(256, 2) gemm_kernel(float* __restrict__ out, int mode)
{
    extern __shared__ __half sb[];
    float* Cs = (float*)sb;                       // [128][132] after mainloop

    const int tid = threadIdx.x, w = tid >> 5, lane = tid & 31;
    const int r0 = blockIdx.y * 128;
    const int nb = blockIdx.x * 128;

    int which, col0;
    const __half* A_h;
    if (mode == 0){ which = nb >> 10; col0 = nb & 1023; A_h = g_xh; }
    else          { which = 3;        col0 = nb;        A_h = g_ath; }
    const __half* W_h = g_wh + (size_t)which*MM;

    const uint32_t ab = smem_u32(sb);

    auto loadc = [&](int c){
        uint32_t st = ab + (uint32_t)(c & 1) * STAGE_BY;
        int ko = c * 64;
        #pragma unroll
        for (int i = 0; i < 4; i++){
            int idx = tid + i*256;                 // 0..1023: 128 rows x 8 segs
            int row = idx >> 3, seg = idx & 7;
            uint32_t so = (uint32_t)(row*144 + seg*16);
            cp16(st + so,          A_h + (size_t)(r0  + row)*DD + ko + seg*8);
            cp16(st + 18432u + so, W_h + (size_t)(col0 + row)*DD + ko + seg*8);
        }
        asm volatile("cp.async.commit_group;");
    };

    wmma::fragment<wmma::accumulator,16,16,16,float> acc[4][2];
    #pragma unroll
    for (int i = 0; i < 4; i++)
        #pragma unroll
        for (int j = 0; j < 2; j++) wmma::fill_fragment(acc[i][j], 0.0f);

    const int wm = (w >> 2) * 64;
    const int wn = (w & 3) * 32;

    loadc(0);
    for (int c = 0; c < NCH; c++){
        if (c < NCH-1){
            loadc(c+1);
            asm volatile("cp.async.wait_group 1;");
        } else {
            asm volatile("cp.async.wait_group 0;");
        }
        __syncthreads();

        const __half* s = sb + (c & 1) * STAGE_EL;
        const __half* sA = s;
        const __half* sB = s + SARR;

        #pragma unroll
        for (int kk = 0; kk < 64; kk += 16){
            wmma::fragment<wmma::matrix_a,16,16,16,__half,wmma::row_major> af[4];
            wmma::fragment<wmma::matrix_b,16,16,16,__half,wmma::col_major> bf[2];
            #pragma unroll
            for (int i = 0; i < 4; i++)
                wmma::load_matrix_sync(af[i], sA + (wm + i*16)*SSTRIDE + kk, SSTRIDE);
            #pragma unroll
            for (int j = 0; j < 2; j++)
                wmma::load_matrix_sync(bf[j], sB + (wn + j*16)*SSTRIDE + kk, SSTRIDE);
            #pragma unroll
            for (int i = 0; i < 4; i++)
                #pragma unroll
                for (int j = 0; j < 2; j++)
                    wmma::mma_sync(acc[i][j], af[i], bf[j], acc[i][j]);
        }
        __syncthreads();
    }

    #pragma unroll
    for (int i = 0; i < 4; i++)
        #pragma unroll
        for (int j = 0; j < 2; j++)
            wmma::store_matrix_sync(Cs + (wm + i*16)*132 + wn + j*16,
                                    acc[i][j], 132, wmma::mem_row_major);
    __syncthreads();

    const float unsc = 0.03125f;   // 1/32
    #pragma unroll
    for (int rr = 0; rr < 16; rr++){
        int row = w*16 + rr;
        int gt = r0 + row;
        float v0 = Cs[row*132 + lane];
        float v1 = Cs[row*132 + lane + 32];
        float v2 = Cs[row*132 + lane + 64];
        float v3 = Cs[row*132 + lane + 96];
        if (mode == 0){
            float s0 = unsc, s1 = unsc;
            if (which < 2){
                float ssa = v0*v0 + v1*v1;
                float ssb = v2*v2 + v3*v3;
                #pragma unroll
                for (int o = 16; o; o >>= 1){
                    ssa += __shfl_xor_sync(0xffffffffu, ssa, o);
                    ssb += __shfl_xor_sync(0xffffffffu, ssb, o);
                }
                s0 = 1.0f / fmaxf(sqrtf(ssa), 1e-6f);
                s1 = 1.0f / fmaxf(sqrtf(ssb), 1e-6f);
            }
            int bq = gt >> 11, t = gt & (TT-1);
            __half* arr = (which==0) ? g_q : ((which==1) ? g_k : g_v);
            int hh0 = col0 >> 6;
            __half* d0 = arr + ((size_t)(bq*HH + hh0  )*TT + t)*HD;
            __half* d1 = arr + ((size_t)(bq*HH + hh0+1)*TT + t)*HD;
            d0[lane]      = __float2half(v0*s0);
            d0[lane + 32] = __float2half(v1*s0);
            d1[lane]      = __float2half(v2*s1);
            d1[lane + 32] = __float2half(v3*s1);
        } else {
            float* d = out + (size_t)gt*DD + nb;
            d[lane]      = v0*unsc;
            d[lane + 32] = v1*unsc;
            d[lane + 64] = v2*unsc;
            d[lane + 96] = v3*unsc;
        }
    }
}

// =====================================================================
// Attention (fp16 wmma, fp32 softmax): 512 threads / 16 warps per block.
// One block per (b,h,64-q tile); phases split 2x finer than R11:
//  QK:  4 row bands x 4 tile-col groups (3 tiles each, live-masked)
//  softmax: 4 rows per warp
//  PV:  4 row bands x 4 col bands (16 cols), 9 live tiles per warp
// smem unchanged: Qs[64][72] Ks[192][72] Vs[192][72] Ssf f32[64][200]
//                 Ps half[64][200]  total 141312 B
// =====================================================================
#define ATTN_SMEM_BYTES 141312

__global__ void __launch_bounds__(512) attn_kernel()
{
    extern __shared__ __half sm[];
    __half* Qs = sm;                          // [64][72]
    __half* Ks = sm + 4608;                   // [192][72]
    __half* Vs = sm + 18432;                  // [192][72]
    float*  Ssf = (float*)(sm + 32256);       // [64][200] f32 (S, later O[64][68])
    __half* Ps  = sm + 57856;                 // [64][200] half

    const int tid = threadIdx.x, w = tid >> 5, lane = tid & 31;
    const int q0 = blockIdx.x * 64;
    const int h  = blockIdx.y, b = blockIdx.z;
    const size_t base = ((size_t)(b*HH + h)*TT)*HD;
    const __half* qb = g_q + base;
    const __half* kb = g_k + base;
    const __half* vb = g_v + base;

    {   // Q: 64 rows x 8 segs = 512 units -> 1 iter
        int row = tid >> 3, seg = tid & 7;
        uint4 v = *(const uint4*)(qb + (size_t)(q0 + row)*HD + seg*8);
        *(uint4*)(Qs + row*72 + seg*8) = v;
    }
    #pragma unroll
    for (int it = 0; it < 3; it++){           // K,V: 192x8 = 1536 units -> 3 iters
        int idx = tid + it*512;
        int row = idx >> 3, seg = idx & 7;
        int jg = q0 + row;
        uint4 kv = make_uint4(0,0,0,0), vv = make_uint4(0,0,0,0);
        if (jg < TT){
            kv = *(const uint4*)(kb + (size_t)jg*HD + seg*8);
            vv = *(const uint4*)(vb + (size_t)jg*HD + seg*8);
        }
        *(uint4*)(Ks + row*72 + seg*8) = kv;
        *(uint4*)(Vs + row*72 + seg*8) = vv;
    }
    __syncthreads();

    const int wr = w & 3;                     // row band (16 rows)
    const int wg = w >> 2;                    // group 0..3

    {   // S = Q @ K^T : warp handles tiles tc = wg*3+f, f<3 (live-masked)
        wmma::fragment<wmma::accumulator,16,16,16,float> acc[3];
        #pragma unroll
        for (int f = 0; f < 3; f++) wmma::fill_fragment(acc[f], 0.0f);
        #pragma unroll
        for (int d = 0; d < HD; d += 16){
            wmma::fragment<wmma::matrix_a,16,16,16,__half,wmma::row_major> af;
            wmma::load_matrix_sync(af, Qs + wr*16*72 + d, 72);
            #pragma unroll
            for (int f = 0; f < 3; f++){
                int tc = wg*3 + f;
                if (tc >= wr && tc <= wr + 8){
                    wmma::fragment<wmma::matrix_b,16,16,16,__half,wmma::col_major> bf;
                    wmma::load_matrix_sync(bf, Ks + tc*16*72 + d, 72);
                    wmma::mma_sync(acc[f], af, bf, acc[f]);
                }
            }
        }
        #pragma unroll
        for (int f = 0; f < 3; f++){
            int tc = wg*3 + f;
            if (tc >= wr && tc <= wr + 8)
                wmma::store_matrix_sync(Ssf + wr*16*200 + tc*16, acc[f], 200,
                                        wmma::mem_row_major);
        }
    }
    __syncthreads();

    // softmax: warp w handles rows w*4 .. w*4+3
    const float slope = exp2f(-8.0f * (float)h / 15.0f);
    #pragma unroll
    for (int rr = 0; rr < 4; rr++){
        int row = w*4 + rr;
        float vals[6];
        float m = -INFINITY;
        #pragma unroll
        for (int i = 0; i < 6; i++){
            int col = lane + 32*i;
            bool ok = (col >= row) && (col < row + WINDOW) && (q0 + col < TT);
            float s = ok ? (Ssf[row*200 + col] - (float)(col - row)*slope) : -INFINITY;
            vals[i] = s;
            m = fmaxf(m, s);
        }
        #pragma unroll
        for (int o = 16; o; o >>= 1) m = fmaxf(m, __shfl_xor_sync(0xffffffffu, m, o));
        float sum = 0.0f;
        #pragma unroll
        for (int i = 0; i < 6; i++){
            float p = (vals[i] > -INFINITY) ? __expf(vals[i] - m) : 0.0f;
            vals[i] = p; sum += p;
        }
        #pragma unroll
        for (int o = 16; o; o >>= 1) sum += __shfl_xor_sync(0xffffffffu, sum, o);
        float inv = 1.0f / sum;
        #pragma unroll
        for (int i = 0; i < 6; i++){
            int col = lane + 32*i;
            Ps[row*200 + col] = __float2half(vals[i]*inv);
        }
    }
    __syncthreads();

    {   // O = P @ V : warp (wr, wg) -> rows wr*16, cols wg*16; 9 live tiles
        wmma::fragment<wmma::accumulator,16,16,16,float> acc;
        wmma::fill_fragment(acc, 0.0f);
        #pragma unroll
        for (int tj = 0; tj < 12; tj++){
            if (tj >= wr && tj <= wr + 8){
                wmma::fragment<wmma::matrix_a,16,16,16,__half,wmma::row_major> af;
                wmma::fragment<wmma::matrix_b,16,16,16,__half,wmma::row_major> bf;
                wmma::load_matrix_sync(af, Ps + wr*16*200 + tj*16, 200);
                wmma::load_matrix_sync(bf, Vs + tj*16*72 + wg*16, 72);
                wmma::mma_sync(acc, af, bf, acc);
            }
        }
        wmma::store_matrix_sync(Ssf + wr*16*68 + wg*16, acc, 68, wmma::mem_row_major);
    }
    __syncthreads();

    #pragma unroll
    for (int it = 0; it < 2; it++){             // write fp16 [B,T,D]: 1024 units
        int idx = tid + it*512;
        int row = idx >> 4, c4 = (idx & 15) << 2;
        float4 v = *(const float4*)(Ssf + row*68 + c4);
        size_t o = (size_t)(b*TT + q0 + row)*DD + h*HD + c4;
        *(half2*)(g_ath+o)   = half2(__float2half(v.x), __float2half(v.y));
        *(half2*)(g_ath+o+2) = half2(__float2half(v.z), __float2half(v.w));
    }
}

// =====================================================================
extern "C" void kernel_launch(void* const* d_in, const int* in_sizes, int n_in,
                              void* d_out, int out_size)
{
    const float* x  = (const float*)d_in[0];
    const float* Wq = (const float*)d_in[1];
    const float* Wk = (const float*)d_in[2];
    const float* Wv = (const float*)d_in[3];
    const float* Wo = (const float*)d_in[4];
    float* out = (float*)d_out;

    cudaFuncSetAttribute(gemm_kernel, cudaFuncAttributeMaxDynamicSharedMemorySize,
                         GEMM_SMEM);
    cudaFuncSetAttribute(attn_kernel, cudaFuncAttributeMaxDynamicSharedMemorySize,
                         ATTN_SMEM_BYTES);

    // 0) fp16 conversion of x and weights (x32)
    split_kernel<<<8192, 256>>>(x, Wq, Wk, Wv, Wo);
    // 1) fused QKV projection + per-head l2norm  [M=4096 x N=3072]
    gemm_kernel<<<dim3(24, 32), 256, GEMM_SMEM>>>(nullptr, 0);
    // 2) sliding-window attention per (b, h, 64-query tile)
    attn_kernel<<<dim3(TT/64, HH, BB), 512, ATTN_SMEM_BYTES>>>();
    // 3) output projection  [M=4096 x N=1024]
    gemm_kernel<<<dim3(8, 32), 256, GEMM_SMEM>>>(out, 1);
}

// round 13
// speedup vs baseline: 2.9917x; 1.0459x over previous
#include <cuda_runtime.h>
#include <cuda_fp16.h>
#include <mma.h>
#include <math.h>
#include <cstdint>

using namespace nvcuda;

#define BB 2
#define TT 2048
#define DD 1024
#define HH 16
#define HD 64
#define NROWS (BB*TT)      // 4096
#define WINDOW 128
#define MM (1024*1024)

// ---------------- scratch (device globals: allocation-free) ----------------
__device__ __half g_q[(size_t)BB*HH*TT*HD];   // normalized q (fp16)
__device__ __half g_k[(size_t)BB*HH*TT*HD];   // normalized k (fp16)
__device__ __half g_v[(size_t)BB*HH*TT*HD];   // v (fp16)
__device__ __half g_xh[(size_t)NROWS*DD];     // x (fp16)
__device__ __half g_wh[(size_t)4*MM];         // 32*W (fp16)
__device__ __half g_ath[(size_t)NROWS*DD];    // attention out (fp16)

__device__ __forceinline__ uint32_t smem_u32(const void* p){
    uint32_t a;
    asm("{ .reg .u64 t; cvta.to.shared.u64 t, %1; cvt.u32.u64 %0, t; }" : "=r"(a) : "l"(p));
    return a;
}
__device__ __forceinline__ void cp16(uint32_t s, const void* g){
    asm volatile("cp.async.cg.shared.global [%0], [%1], 16;" :: "r"(s), "l"(g));
}

// =====================================================================
// split prep: x -> fp16 ; W -> fp16(32*W)
// =====================================================================
__global__ void __launch_bounds__(256) split_kernel(
    const float* __restrict__ x,
    const float* __restrict__ wq, const float* __restrict__ wk,
    const float* __restrict__ wv, const float* __restrict__ wo)
{
    size_t fi = (size_t)blockIdx.x*256 + threadIdx.x;
    if (fi < 1048576){
        float4 v = ((const float4*)x)[fi];
        size_t e = fi*4;
        *(half2*)(g_xh+e)   = half2(__float2half(v.x), __float2half(v.y));
        *(half2*)(g_xh+e+2) = half2(__float2half(v.z), __float2half(v.w));
    } else {
        size_t r = fi - 1048576;
        int m = (int)(r >> 18);
        size_t base = r & 262143;
        const float* src = (m==0)?wq:(m==1)?wk:(m==2)?wv:wo;
        float4 v = ((const float4*)src)[base];
        size_t e = (size_t)m*MM + base*4;
        *(half2*)(g_wh+e)   = half2(__float2half(32.0f*v.x), __float2half(32.0f*v.y));
        *(half2*)(g_wh+e+2) = half2(__float2half(32.0f*v.z), __float2half(32.0f*v.w));
    }
}

// =====================================================================
// GEMM (plain fp16, fp32 acc), 2 CTAs/SM. CTA 128x128, warp 64x32, BK=64.
// (unchanged — at the legacy-HMMA instruction-rate ceiling)
// =====================================================================
#define NCH 16
#define SSTRIDE 72
#define SARR 9216                        // 128 rows x 72 el
#define STAGE_EL (2*SARR)                // 18432 el
#define STAGE_BY (STAGE_EL*2)            // 36864 B
#define GEMM_SMEM 73728

__global__ void __launch_bounds__(256, 2) gemm_kernel(float* __restrict__ out, int mode)
{
    extern __shared__ __half sb[];
    float* Cs = (float*)sb;                       // [128][132] after mainloop

    const int tid = threadIdx.x, w = tid >> 5, lane = tid & 31;
    const int r0 = blockIdx.y * 128;
    const int nb = blockIdx.x * 128;

    int which, col0;
    const __half* A_h;
    if (mode == 0){ which = nb >> 10; col0 = nb & 1023; A_h = g_xh; }
    else          { which = 3;        col0 = nb;        A_h = g_ath; }
    const __half* W_h = g_wh + (size_t)which*MM;

    const uint32_t ab = smem_u32(sb);

    auto loadc = [&](int c){
        uint32_t st = ab + (uint32_t)(c & 1) * STAGE_BY;
        int ko = c * 64;
        #pragma unroll
        for (int i = 0; i < 4; i++){
            int idx = tid + i*256;
            int row = idx >> 3, seg = idx & 7;
            uint32_t so = (uint32_t)(row*144 + seg*16);
            cp16(st + so,          A_h + (size_t)(r0  + row)*DD + ko + seg*8);
            cp16(st + 18432u + so, W_h + (size_t)(col0 + row)*DD + ko + seg*8);
        }
        asm volatile("cp.async.commit_group;");
    };

    wmma::fragment<wmma::accumulator,16,16,16,float> acc[4][2];
    #pragma unroll
    for (int i = 0; i < 4; i++)
        #pragma unroll
        for (int j = 0; j < 2; j++) wmma::fill_fragment(acc[i][j], 0.0f);

    const int wm = (w >> 2) * 64;
    const int wn = (w & 3) * 32;

    loadc(0);
    for (int c = 0; c < NCH; c++){
        if (c < NCH-1){
            loadc(c+1);
            asm volatile("cp.async.wait_group 1;");
        } else {
            asm volatile("cp.async.wait_group 0;");
        }
        __syncthreads();

        const __half* s = sb + (c & 1) * STAGE_EL;
        const __half* sA = s;
        const __half* sB = s + SARR;

        #pragma unroll
        for (int kk = 0; kk < 64; kk += 16){
            wmma::fragment<wmma::matrix_a,16,16,16,__half,wmma::row_major> af[4];
            wmma::fragment<wmma::matrix_b,16,16,16,__half,wmma::col_major> bf[2];
            #pragma unroll
            for (int i = 0; i < 4; i++)
                wmma::load_matrix_sync(af[i], sA + (wm + i*16)*SSTRIDE + kk, SSTRIDE);
            #pragma unroll
            for (int j = 0; j < 2; j++)
                wmma::load_matrix_sync(bf[j], sB + (wn + j*16)*SSTRIDE + kk, SSTRIDE);
            #pragma unroll
            for (int i = 0; i < 4; i++)
                #pragma unroll
                for (int j = 0; j < 2; j++)
                    wmma::mma_sync(acc[i][j], af[i], bf[j], acc[i][j]);
        }
        __syncthreads();
    }

    #pragma unroll
    for (int i = 0; i < 4; i++)
        #pragma unroll
        for (int j = 0; j < 2; j++)
            wmma::store_matrix_sync(Cs + (wm + i*16)*132 + wn + j*16,
                                    acc[i][j], 132, wmma::mem_row_major);
    __syncthreads();

    const float unsc = 0.03125f;   // 1/32
    #pragma unroll
    for (int rr = 0; rr < 16; rr++){
        int row = w*16 + rr;
        int gt = r0 + row;
        float v0 = Cs[row*132 + lane];
        float v1 = Cs[row*132 + lane + 32];
        float v2 = Cs[row*132 + lane + 64];
        float v3 = Cs[row*132 + lane + 96];
        if (mode == 0){
            float s0 = unsc, s1 = unsc;
            if (which < 2){
                float ssa = v0*v0 + v1*v1;
                float ssb = v2*v2 + v3*v3;
                #pragma unroll
                for (int o = 16; o; o >>= 1){
                    ssa += __shfl_xor_sync(0xffffffffu, ssa, o);
                    ssb += __shfl_xor_sync(0xffffffffu, ssb, o);
                }
                s0 = 1.0f / fmaxf(sqrtf(ssa), 1e-6f);
                s1 = 1.0f / fmaxf(sqrtf(ssb), 1e-6f);
            }
            int bq = gt >> 11, t = gt & (TT-1);
            __half* arr = (which==0) ? g_q : ((which==1) ? g_k : g_v);
            int hh0 = col0 >> 6;
            __half* d0 = arr + ((size_t)(bq*HH + hh0  )*TT + t)*HD;
            __half* d1 = arr + ((size_t)(bq*HH + hh0+1)*TT + t)*HD;
            d0[lane]      = __float2half(v0*s0);
            d0[lane + 32] = __float2half(v1*s0);
            d1[lane]      = __float2half(v2*s1);
            d1[lane + 32] = __float2half(v3*s1);
        } else {
            float* d = out + (size_t)gt*DD + nb;
            d[lane]      = v0*unsc;
            d[lane + 32] = v1*unsc;
            d[lane + 64] = v2*unsc;
            d[lane + 96] = v3*unsc;
        }
    }
}

// =====================================================================
// Attention (fp16 wmma), 512 threads, 2 BLOCKS/SM (90KB smem).
// S = q.k in [-1,1] -> fp16 accumulator, stored half. Softmax reads S
// (half) and writes P IN PLACE (reads precede warp-sync shuffles).
// O staged fp32 into dead K region.
// smem: Qs[64][72]h Ks[192][72]h Vs[192][72]h Sh[64][200]h = 90112 B
// =====================================================================
#define ATTN_SMEM_BYTES 90112

__global__ void __launch_bounds__(512, 2) attn_kernel()
{
    extern __shared__ __half sm[];
    __half* Qs = sm;                          // [64][72]
    __half* Ks = sm + 4608;                   // [192][72] (dead after QK)
    __half* Vs = sm + 18432;                  // [192][72]
    __half* Sh = sm + 32256;                  // [64][200] half: S, then P in place
    float*  Os = (float*)(sm + 4608);         // [64][68] f32, overlays Ks

    const int tid = threadIdx.x, w = tid >> 5, lane = tid & 31;
    const int q0 = blockIdx.x * 64;
    const int h  = blockIdx.y, b = blockIdx.z;
    const size_t base = ((size_t)(b*HH + h)*TT)*HD;
    const __half* qb = g_q + base;
    const __half* kb = g_k + base;
    const __half* vb = g_v + base;

    {   // Q: 64 rows x 8 segs = 512 units
        int row = tid >> 3, seg = tid & 7;
        uint4 v = *(const uint4*)(qb + (size_t)(q0 + row)*HD + seg*8);
        *(uint4*)(Qs + row*72 + seg*8) = v;
    }
    #pragma unroll
    for (int it = 0; it < 3; it++){           // K,V: 192x8 = 1536 units
        int idx = tid + it*512;
        int row = idx >> 3, seg = idx & 7;
        int jg = q0 + row;
        uint4 kv = make_uint4(0,0,0,0), vv = make_uint4(0,0,0,0);
        if (jg < TT){
            kv = *(const uint4*)(kb + (size_t)jg*HD + seg*8);
            vv = *(const uint4*)(vb + (size_t)jg*HD + seg*8);
        }
        *(uint4*)(Ks + row*72 + seg*8) = kv;
        *(uint4*)(Vs + row*72 + seg*8) = vv;
    }
    __syncthreads();

    const int wr = w & 3;                     // row band (16 rows)
    const int wg = w >> 2;                    // group 0..3

    {   // S = Q @ K^T, fp16 accumulators, live tiles tc = wg*3+f
        wmma::fragment<wmma::accumulator,16,16,16,__half> acc[3];
        #pragma unroll
        for (int f = 0; f < 3; f++) wmma::fill_fragment(acc[f], __float2half(0.0f));
        #pragma unroll
        for (int d = 0; d < HD; d += 16){
            wmma::fragment<wmma::matrix_a,16,16,16,__half,wmma::row_major> af;
            wmma::load_matrix_sync(af, Qs + wr*16*72 + d, 72);
            #pragma unroll
            for (int f = 0; f < 3; f++){
                int tc = wg*3 + f;
                if (tc >= wr && tc <= wr + 8){
                    wmma::fragment<wmma::matrix_b,16,16,16,__half,wmma::col_major> bf;
                    wmma::load_matrix_sync(bf, Ks + tc*16*72 + d, 72);
                    wmma::mma_sync(acc[f], af, bf, acc[f]);
                }
            }
        }
        #pragma unroll
        for (int f = 0; f < 3; f++){
            int tc = wg*3 + f;
            if (tc >= wr && tc <= wr + 8)
                wmma::store_matrix_sync(Sh + wr*16*200 + tc*16, acc[f], 200,
                                        wmma::mem_row_major);
        }
    }
    __syncthreads();

    // softmax: warp w handles rows w*4 .. w*4+3; P overwrites S in place
    const float slope = exp2f(-8.0f * (float)h / 15.0f);
    #pragma unroll
    for (int rr = 0; rr < 4; rr++){
        int row = w*4 + rr;
        float vals[6];
        float m = -INFINITY;
        #pragma unroll
        for (int i = 0; i < 6; i++){
            int col = lane + 32*i;
            bool ok = (col >= row) && (col < row + WINDOW) && (q0 + col < TT);
            float s = ok ? (__half2float(Sh[row*200 + col]) - (float)(col - row)*slope)
                         : -INFINITY;
            vals[i] = s;
            m = fmaxf(m, s);
        }
        #pragma unroll
        for (int o = 16; o; o >>= 1) m = fmaxf(m, __shfl_xor_sync(0xffffffffu, m, o));
        float sum = 0.0f;
        #pragma unroll
        for (int i = 0; i < 6; i++){
            float p = (vals[i] > -INFINITY) ? __expf(vals[i] - m) : 0.0f;
            vals[i] = p; sum += p;
        }
        #pragma unroll
        for (int o = 16; o; o >>= 1) sum += __shfl_xor_sync(0xffffffffu, sum, o);
        float inv = 1.0f / sum;
        #pragma unroll
        for (int i = 0; i < 6; i++){
            int col = lane + 32*i;
            Sh[row*200 + col] = __float2half(vals[i]*inv);   // in-place P
        }
    }
    __syncthreads();

    {   // O = P @ V : warp (wr, wg) -> rows wr*16, cols wg*16; 9 live tiles
        wmma::fragment<wmma::accumulator,16,16,16,float> acc;
        wmma::fill_fragment(acc, 0.0f);
        #pragma unroll
        for (int tj = 0; tj < 12; tj++){
            if (tj >= wr && tj <= wr + 8){
                wmma::fragment<wmma::matrix_a,16,16,16,__half,wmma::row_major> af;
                wmma::fragment<wmma::matrix_b,16,16,16,__half,wmma::row_major> bf;
                wmma::load_matrix_sync(af, Sh + wr*16*200 + tj*16, 200);
                wmma::load_matrix_sync(bf, Vs + tj*16*72 + wg*16, 72);
                wmma::mma_sync(acc, af, bf, acc);
            }
        }
        wmma::store_matrix_sync(Os + wr*16*68 + wg*16, acc, 68, wmma::mem_row_major);
    }
    __syncthreads();

    #pragma unroll
    for (int it = 0; it < 2; it++){             // write fp16 [B,T,D]
        int idx = tid + it*512;
        int row = idx >> 4, c4 = (idx & 15) << 2;
        float4 v = *(const float4*)(Os + row*68 + c4);
        size_t o = (size_t)(b*TT + q0 + row)*DD + h*HD + c4;
        *(half2*)(g_ath+o)   = half2(__float2half(v.x), __float2half(v.y));
        *(half2*)(g_ath+o+2) = half2(__float2half(v.z), __float2half(v.w));
    }
}

// =====================================================================
extern "C" void kernel_launch(void* const* d_in, const int* in_sizes, int n_in,
                              void* d_out, int out_size)
{
    const float* x  = (const float*)d_in[0];
    const float* Wq = (const float*)d_in[1];
    const float* Wk = (const float*)d_in[2];
    const float* Wv = (const float*)d_in[3];
    const float* Wo = (const float*)d_in[4];
    float* out = (float*)d_out;

    cudaFuncSetAttribute(gemm_kernel, cudaFuncAttributeMaxDynamicSharedMemorySize,
                         GEMM_SMEM);
    cudaFuncSetAttribute(attn_kernel, cudaFuncAttributeMaxDynamicSharedMemorySize,
                         ATTN_SMEM_BYTES);

    // 0) fp16 conversion of x and weights (x32)
    split_kernel<<<8192, 256>>>(x, Wq, Wk, Wv, Wo);
    // 1) fused QKV projection + per-head l2norm  [M=4096 x N=3072]
    gemm_kernel<<<dim3(24, 32), 256, GEMM_SMEM>>>(nullptr, 0);
    // 2) sliding-window attention per (b, h, 64-query tile)
    attn_kernel<<<dim3(TT/64, HH, BB), 512, ATTN_SMEM_BYTES>>>();
    // 3) output projection  [M=4096 x N=1024]
    gemm_kernel<<<dim3(8, 32), 256, GEMM_SMEM>>>(out, 1);
}